// round 2
// baseline (speedup 1.0000x reference)
#include <cuda_runtime.h>
#include <cstdint>
#include <math.h>

// ---------------- problem constants ----------------
#define D_MODEL 1024
#define HEADS   8
#define DH      128
#define DEPTH   2
#define BATCH   2
#define TOKENS  2048
#define GRP     128            // tokens per relay group
#define NGRP    16             // groups
#define SEQ     2064           // stitched length per batch = NGRP*(GRP+1)
#define MROWS   (BATCH*SEQ)    // 4128
#define DFF     4096

// ---------------- scratch (floats), addressed by offset in-device --------
#define OFF_XS    0L
#define SZ_XS     ((long)MROWS*D_MODEL)
#define OFF_Y     (OFF_XS + SZ_XS)
#define SZ_Y      ((long)MROWS*D_MODEL)
#define OFF_QKV   (OFF_Y + SZ_Y)
#define SZ_QKV    ((long)MROWS*3*D_MODEL)
#define OFF_ATT   (OFF_QKV + SZ_QKV)
#define SZ_ATT    ((long)MROWS*D_MODEL)
#define OFF_FFN   (OFF_ATT + SZ_ATT)
#define SZ_FFN    ((long)MROWS*DFF)
#define OFF_RLN   (OFF_FFN + SZ_FFN)
#define SZ_RLN    (32L*D_MODEL)
#define OFF_RQKV  (OFF_RLN + SZ_RLN)
#define SZ_RQKV   (32L*3*D_MODEL)
#define OFF_RATT  (OFF_RQKV + SZ_RQKV)
#define SZ_RATT   (32L*D_MODEL)
#define OFF_RPRJ  (OFF_RATT + SZ_RATT)
#define SZ_RPRJ   (32L*D_MODEL)
#define SCRATCH_FLOATS (OFF_RPRJ + SZ_RPRJ)

__device__ float g_scratch[SCRATCH_FLOATS];

// ---------------- GEMM: C = A(MxK) @ B(KxN), row-major, fused epilogues ---
// EP bits: 1 = +bias, 2 = residual accumulate into C, 4 = leaky_relu(0.01)
#define TM 128
#define TN 128
#define TK 8

template<int EP>
__global__ __launch_bounds__(256)
void gemm_f32(long a_off, const float* __restrict__ B,
              const float* __restrict__ bias, long c_off,
              int M, int N, int K)
{
    const float* __restrict__ A = g_scratch + a_off;
    float* __restrict__ C = g_scratch + c_off;

    __shared__ float As[TK][TM];
    __shared__ float Bs[TK][TN];

    const int tid = threadIdx.x;
    const int bm = blockIdx.y * TM;
    const int bn = blockIdx.x * TN;
    const int tx = tid & 15;
    const int ty = tid >> 4;

    const int a_r = tid >> 1;
    const int a_c = (tid & 1) * 4;
    const int b_r = tid >> 5;
    const int b_c = (tid & 31) * 4;

    int a_row = bm + a_r;
    if (a_row >= M) a_row = M - 1;   // clamp; garbage rows never stored

    float acc[8][8];
    #pragma unroll
    for (int i = 0; i < 8; i++)
        #pragma unroll
        for (int j = 0; j < 8; j++) acc[i][j] = 0.f;

    for (int k0 = 0; k0 < K; k0 += TK) {
        float4 av = *reinterpret_cast<const float4*>(A + (size_t)a_row * K + k0 + a_c);
        As[a_c + 0][a_r] = av.x;
        As[a_c + 1][a_r] = av.y;
        As[a_c + 2][a_r] = av.z;
        As[a_c + 3][a_r] = av.w;
        *reinterpret_cast<float4*>(&Bs[b_r][b_c]) =
            *reinterpret_cast<const float4*>(B + (size_t)(k0 + b_r) * N + bn + b_c);
        __syncthreads();

        #pragma unroll
        for (int kk = 0; kk < TK; kk++) {
            float a[8], b[8];
            *reinterpret_cast<float4*>(&a[0]) = *reinterpret_cast<float4*>(&As[kk][ty * 8]);
            *reinterpret_cast<float4*>(&a[4]) = *reinterpret_cast<float4*>(&As[kk][ty * 8 + 4]);
            *reinterpret_cast<float4*>(&b[0]) = *reinterpret_cast<float4*>(&Bs[kk][tx * 8]);
            *reinterpret_cast<float4*>(&b[4]) = *reinterpret_cast<float4*>(&Bs[kk][tx * 8 + 4]);
            #pragma unroll
            for (int i = 0; i < 8; i++)
                #pragma unroll
                for (int j = 0; j < 8; j++)
                    acc[i][j] += a[i] * b[j];
        }
        __syncthreads();
    }

    #pragma unroll
    for (int i = 0; i < 8; i++) {
        int row = bm + ty * 8 + i;
        if (row >= M) break;
        float* crow = C + (size_t)row * N + bn + tx * 8;
        #pragma unroll
        for (int j = 0; j < 8; j += 4) {
            float4 r = make_float4(acc[i][j], acc[i][j+1], acc[i][j+2], acc[i][j+3]);
            if (EP & 1) {
                float4 bb = *reinterpret_cast<const float4*>(bias + bn + tx * 8 + j);
                r.x += bb.x; r.y += bb.y; r.z += bb.z; r.w += bb.w;
            }
            if (EP & 4) {
                r.x = r.x > 0.f ? r.x : 0.01f * r.x;
                r.y = r.y > 0.f ? r.y : 0.01f * r.y;
                r.z = r.z > 0.f ? r.z : 0.01f * r.z;
                r.w = r.w > 0.f ? r.w : 0.01f * r.w;
            }
            if (EP & 2) {
                float4 c0 = *reinterpret_cast<float4*>(crow + j);
                r.x += c0.x; r.y += c0.y; r.z += c0.z; r.w += c0.w;
            }
            *reinterpret_cast<float4*>(crow + j) = r;
        }
    }
}

// ---------------- LayerNorm (row length 1024), strided, scratch->scratch --
__global__ __launch_bounds__(256)
void ln_kernel(long in_off, long out_off,
               const float* __restrict__ gamma, const float* __restrict__ beta,
               long in_stride, long out_stride)
{
    const float* __restrict__ in = g_scratch + in_off;
    float* __restrict__ out = g_scratch + out_off;

    const int row = blockIdx.x;
    const int tid = threadIdx.x;
    const float4 v = reinterpret_cast<const float4*>(in + (size_t)row * in_stride)[tid];

    float s  = v.x + v.y + v.z + v.w;
    float sq = v.x*v.x + v.y*v.y + v.z*v.z + v.w*v.w;
    #pragma unroll
    for (int o = 16; o > 0; o >>= 1) {
        s  += __shfl_xor_sync(0xffffffffu, s,  o);
        sq += __shfl_xor_sync(0xffffffffu, sq, o);
    }
    __shared__ float ss[8], sqs[8];
    const int warp = tid >> 5;
    if ((tid & 31) == 0) { ss[warp] = s; sqs[warp] = sq; }
    __syncthreads();
    float ts = 0.f, tq = 0.f;
    #pragma unroll
    for (int w = 0; w < 8; w++) { ts += ss[w]; tq += sqs[w]; }
    const float mean = ts * (1.0f / D_MODEL);
    const float var  = tq * (1.0f / D_MODEL) - mean * mean;
    const float rstd = rsqrtf(var + 1e-5f);

    const float4 g4 = reinterpret_cast<const float4*>(gamma)[tid];
    const float4 b4 = reinterpret_cast<const float4*>(beta)[tid];
    float4 o;
    o.x = (v.x - mean) * rstd * g4.x + b4.x;
    o.y = (v.y - mean) * rstd * g4.y + b4.y;
    o.z = (v.z - mean) * rstd * g4.z + b4.z;
    o.w = (v.w - mean) * rstd * g4.w + b4.w;
    reinterpret_cast<float4*>(out + (size_t)row * out_stride)[tid] = o;
}

// ---------------- flash attention (unscaled dots!), dh=128 ---------------
// Br=32 q-rows per block, Bc=32 kv per tile, K/V share one smem buffer.
// grid: (ceil(S/32), HEADS, BATCH), block 256. Static smem ~34KB.
#define FA_BR 32
#define FA_BC 32
#define FA_PAD 132   // 132 floats/row => conflict-free column reads

__global__ __launch_bounds__(256)
void flash_attn(long qkv_off, long out_off, int S)
{
    __shared__ float Qs[FA_BR][FA_PAD];
    __shared__ float KVs[FA_BC][FA_PAD];

    const float* __restrict__ qkv = g_scratch + qkv_off;
    float* __restrict__ out = g_scratch + out_off;

    const int b = blockIdx.z, h = blockIdx.y;
    const int q0 = blockIdx.x * FA_BR;
    const int tid = threadIdx.x;
    const int tx = tid & 31;      // kv-column lane / out-column group
    const int ty = tid >> 5;      // warp id = q-row group (4 rows each)
    const float* base = qkv + (size_t)b * S * (3 * D_MODEL);

    // load Q tile: 32 rows x 32 float4
    #pragma unroll
    for (int it = 0; it < 4; it++) {
        int idx = it * 256 + tid;
        int r = idx >> 5, c4 = (idx & 31) * 4;
        int qr = q0 + r; if (qr >= S) qr = S - 1;
        *reinterpret_cast<float4*>(&Qs[r][c4]) =
            *reinterpret_cast<const float4*>(base + (size_t)qr * (3*D_MODEL) + h * DH + c4);
    }

    float m_run[4], l_run[4], acc[4][4];
    #pragma unroll
    for (int i = 0; i < 4; i++) {
        m_run[i] = -1e30f; l_run[i] = 0.f;
        #pragma unroll
        for (int j = 0; j < 4; j++) acc[i][j] = 0.f;
    }

    for (int kt0 = 0; kt0 < S; kt0 += FA_BC) {
        __syncthreads();    // prior PV reads of KVs done (first iter: Q store visible too)
        // load K tile
        #pragma unroll
        for (int it = 0; it < 4; it++) {
            int idx = it * 256 + tid;
            int r = idx >> 5, c4 = (idx & 31) * 4;
            int kr = kt0 + r; if (kr >= S) kr = S - 1;
            *reinterpret_cast<float4*>(&KVs[r][c4]) =
                *reinterpret_cast<const float4*>(base + (size_t)kr * (3*D_MODEL) + D_MODEL + h * DH + c4);
        }
        __syncthreads();

        // S tile: sv[i] = Q[ty*4+i] . K[tx]  (NO 1/sqrt(d) scaling)
        float sv[4] = {0.f, 0.f, 0.f, 0.f};
        #pragma unroll 4
        for (int d = 0; d < DH; d += 4) {
            float4 kv = *reinterpret_cast<float4*>(&KVs[tx][d]);
            #pragma unroll
            for (int i = 0; i < 4; i++) {
                float4 qv = *reinterpret_cast<float4*>(&Qs[ty * 4 + i][d]);
                sv[i] += qv.x*kv.x + qv.y*kv.y + qv.z*kv.z + qv.w*kv.w;
            }
        }

        const bool valid = (kt0 + tx) < S;
        float p_reg[4];
        #pragma unroll
        for (int i = 0; i < 4; i++) {
            float s = valid ? sv[i] : -1e30f;
            float mx = s;
            #pragma unroll
            for (int o = 16; o > 0; o >>= 1)
                mx = fmaxf(mx, __shfl_xor_sync(0xffffffffu, mx, o));
            const float mnew = fmaxf(m_run[i], mx);
            const float scale = __expf(m_run[i] - mnew);
            float p = __expf(s - mnew);           // masked lanes underflow to 0
            float rs = p;
            #pragma unroll
            for (int o = 16; o > 0; o >>= 1)
                rs += __shfl_xor_sync(0xffffffffu, rs, o);
            l_run[i] = l_run[i] * scale + rs;
            m_run[i] = mnew;
            #pragma unroll
            for (int j = 0; j < 4; j++) acc[i][j] *= scale;
            p_reg[i] = p;
        }

        __syncthreads();    // all S-reads of KVs done before V overwrites it
        // load V tile into same buffer
        #pragma unroll
        for (int it = 0; it < 4; it++) {
            int idx = it * 256 + tid;
            int r = idx >> 5, c4 = (idx & 31) * 4;
            int kr = kt0 + r; if (kr >= S) kr = S - 1;
            *reinterpret_cast<float4*>(&KVs[r][c4]) =
                *reinterpret_cast<const float4*>(base + (size_t)kr * (3*D_MODEL) + 2 * D_MODEL + h * DH + c4);
        }
        __syncthreads();

        // PV: acc[i][0..3] over cols tx*4..tx*4+3; P broadcast via shuffle
        #pragma unroll 8
        for (int k = 0; k < FA_BC; k++) {
            float4 vv = *reinterpret_cast<float4*>(&KVs[k][tx * 4]);
            #pragma unroll
            for (int i = 0; i < 4; i++) {
                float p = __shfl_sync(0xffffffffu, p_reg[i], k);
                acc[i][0] += p * vv.x; acc[i][1] += p * vv.y;
                acc[i][2] += p * vv.z; acc[i][3] += p * vv.w;
            }
        }
    }

    #pragma unroll
    for (int i = 0; i < 4; i++) {
        int row = q0 + ty * 4 + i;
        if (row >= S) continue;
        float inv_l = 1.0f / l_run[i];
        float4 o = make_float4(acc[i][0]*inv_l, acc[i][1]*inv_l,
                               acc[i][2]*inv_l, acc[i][3]*inv_l);
        *reinterpret_cast<float4*>(out + (size_t)(b * S + row) * D_MODEL + h * DH + tx * 4) = o;
    }
}

// ---------------- relay attention (16 tokens, 8 heads, dh=128) -----------
__global__ __launch_bounds__(128)
void relay_attn(long rqkv_off, long ratt_off)
{
    const float* __restrict__ rqkv = g_scratch + rqkv_off;
    float* __restrict__ rattn = g_scratch + ratt_off;

    const int h = blockIdx.x, b = blockIdx.y;
    __shared__ float q[16][128], k[16][128], v[16][128];
    __shared__ float p[16][16];
    const int tid = threadIdx.x;

    #pragma unroll
    for (int it = 0; it < 4; it++) {
        int idx4 = it * 128 + tid;
        int r = idx4 >> 5, c = (idx4 & 31) * 4;
        const float* rowp = rqkv + (size_t)(b * 16 + r) * (3 * D_MODEL);
        *reinterpret_cast<float4*>(&q[r][c]) = *reinterpret_cast<const float4*>(rowp + h * DH + c);
        *reinterpret_cast<float4*>(&k[r][c]) = *reinterpret_cast<const float4*>(rowp + D_MODEL + h * DH + c);
        *reinterpret_cast<float4*>(&v[r][c]) = *reinterpret_cast<const float4*>(rowp + 2 * D_MODEL + h * DH + c);
    }
    __syncthreads();

    #pragma unroll
    for (int t = 0; t < 2; t++) {
        int ij = tid * 2 + t;
        int i = ij >> 4, j = ij & 15;
        float s = 0.f;
        for (int d = 0; d < 128; d += 4) {
            float4 qa = *reinterpret_cast<float4*>(&q[i][d]);
            float4 ka = *reinterpret_cast<float4*>(&k[j][d]);
            s += qa.x*ka.x + qa.y*ka.y + qa.z*ka.z + qa.w*ka.w;
        }
        p[i][j] = s;
    }
    __syncthreads();

    if (tid < 16) {
        float mx = -1e30f;
        #pragma unroll
        for (int j = 0; j < 16; j++) mx = fmaxf(mx, p[tid][j]);
        float sum = 0.f; float e[16];
        #pragma unroll
        for (int j = 0; j < 16; j++) { e[j] = __expf(p[tid][j] - mx); sum += e[j]; }
        float inv = 1.0f / sum;
        #pragma unroll
        for (int j = 0; j < 16; j++) p[tid][j] = e[j] * inv;
    }
    __syncthreads();

    const int i = tid >> 3, c0 = (tid & 7) * 16;
    #pragma unroll
    for (int c = 0; c < 16; c++) {
        float o = 0.f;
        #pragma unroll
        for (int j = 0; j < 16; j++) o += p[i][j] * v[j][c0 + c];
        rattn[(size_t)(b * 16 + i) * D_MODEL + h * DH + c0 + c] = o;
    }
}

// ---------------- small glue kernels ----------------
__global__ void init_xs(const float* __restrict__ x, const float* __restrict__ relay_emb)
{
    float* __restrict__ xs = g_scratch + OFF_XS;
    const int row = blockIdx.x;               // 0..MROWS-1
    const int b = row / SEQ, sr = row % SEQ;
    const int grp = sr / (GRP + 1), w = sr % (GRP + 1);
    float4 val;
    if (w == 0)
        val = reinterpret_cast<const float4*>(relay_emb)[threadIdx.x];
    else {
        int t = grp * GRP + (w - 1);
        val = reinterpret_cast<const float4*>(x + (size_t)(b * TOKENS + t) * D_MODEL)[threadIdx.x];
    }
    reinterpret_cast<float4*>(xs + (size_t)row * D_MODEL)[threadIdx.x] = val;
}

__global__ void relay_scatter(long rprj_off, const float* __restrict__ bias)
{
    const float* __restrict__ rproj = g_scratch + rprj_off;
    float* __restrict__ xs = g_scratch + OFF_XS;
    const int row = blockIdx.x;               // 0..31 -> xs row = row*129
    float4 r = reinterpret_cast<const float4*>(rproj + (size_t)row * D_MODEL)[threadIdx.x];
    float4 bb = reinterpret_cast<const float4*>(bias)[threadIdx.x];
    float4* dst = reinterpret_cast<float4*>(xs + (size_t)row * (GRP + 1) * D_MODEL) + threadIdx.x;
    float4 c = *dst;
    c.x += r.x + bb.x; c.y += r.y + bb.y; c.z += r.z + bb.z; c.w += r.w + bb.w;
    *dst = c;
}

__global__ void final_out(float* __restrict__ out)
{
    const float* __restrict__ xs = g_scratch + OFF_XS;
    const int row = blockIdx.x;               // 0..B*TOKENS-1
    const int b = row / TOKENS, t = row % TOKENS;
    const int src = b * SEQ + (t >> 7) * (GRP + 1) + 1 + (t & 127);
    reinterpret_cast<float4*>(out + (size_t)row * D_MODEL)[threadIdx.x] =
        reinterpret_cast<const float4*>(xs + (size_t)src * D_MODEL)[threadIdx.x];
}

// ---------------- host side ----------------
static void launch_gemm(int ep, long a_off, const float* B, const float* bias,
                        long c_off, int M, int N, int K)
{
    dim3 grid(N / TN, (M + TM - 1) / TM);
    switch (ep) {
        case 0: gemm_f32<0><<<grid, 256>>>(a_off, B, bias, c_off, M, N, K); break;
        case 3: gemm_f32<3><<<grid, 256>>>(a_off, B, bias, c_off, M, N, K); break;
        case 5: gemm_f32<5><<<grid, 256>>>(a_off, B, bias, c_off, M, N, K); break;
    }
}

extern "C" void kernel_launch(void* const* d_in, const int* in_sizes, int n_in,
                              void* d_out, int out_size)
{
    const float* x         = (const float*)d_in[0];
    const float* relay_emb = (const float*)d_in[1];
    const float* r_ln_g    = (const float*)d_in[2];
    const float* r_ln_b    = (const float*)d_in[3];
    const float* r_qkv     = (const float*)d_in[4];
    const float* r_ow      = (const float*)d_in[5];
    const float* r_ob      = (const float*)d_in[6];
    const float* l_ln_g    = (const float*)d_in[7];
    const float* l_ln_b    = (const float*)d_in[8];
    const float* l_qkv     = (const float*)d_in[9];
    const float* l_ow      = (const float*)d_in[10];
    const float* l_ob      = (const float*)d_in[11];
    const float* f_ln_g    = (const float*)d_in[12];
    const float* f_ln_b    = (const float*)d_in[13];
    const float* f_w1      = (const float*)d_in[14];
    const float* f_b1      = (const float*)d_in[15];
    const float* f_w2      = (const float*)d_in[16];
    const float* f_b2      = (const float*)d_in[17];

    init_xs<<<MROWS, 256>>>(x, relay_emb);

    for (int l = 0; l < DEPTH; l++) {
        const float* rqkv_w = r_qkv + (size_t)l * D_MODEL * 3 * D_MODEL;
        const float* row_w  = r_ow  + (size_t)l * D_MODEL * D_MODEL;
        const float* lqkv_w = l_qkv + (size_t)l * D_MODEL * 3 * D_MODEL;
        const float* low_w  = l_ow  + (size_t)l * D_MODEL * D_MODEL;
        const float* w1     = f_w1  + (size_t)l * D_MODEL * DFF;
        const float* w2     = f_w2  + (size_t)l * DFF * D_MODEL;

        // ---- relay attention over the 16 relay tokens per batch ----
        ln_kernel<<<32, 256>>>(OFF_XS, OFF_RLN, r_ln_g + l * D_MODEL, r_ln_b + l * D_MODEL,
                               (long)(GRP + 1) * D_MODEL, D_MODEL);
        launch_gemm(0, OFF_RLN, rqkv_w, nullptr, OFF_RQKV, 32, 3 * D_MODEL, D_MODEL);
        relay_attn<<<dim3(HEADS, BATCH), 128>>>(OFF_RQKV, OFF_RATT);
        launch_gemm(0, OFF_RATT, row_w, nullptr, OFF_RPRJ, 32, D_MODEL, D_MODEL);
        relay_scatter<<<32, 256>>>(OFF_RPRJ, r_ob + l * D_MODEL);

        // ---- full attention over stitched sequence (2064 per batch) ----
        ln_kernel<<<MROWS, 256>>>(OFF_XS, OFF_Y, l_ln_g + l * D_MODEL, l_ln_b + l * D_MODEL,
                                  D_MODEL, D_MODEL);
        launch_gemm(0, OFF_Y, lqkv_w, nullptr, OFF_QKV, MROWS, 3 * D_MODEL, D_MODEL);
        flash_attn<<<dim3((SEQ + FA_BR - 1) / FA_BR, HEADS, BATCH), 256>>>(OFF_QKV, OFF_ATT, SEQ);
        launch_gemm(3, OFF_ATT, low_w, l_ob + l * D_MODEL, OFF_XS, MROWS, D_MODEL, D_MODEL);

        // ---- FFN ----
        ln_kernel<<<MROWS, 256>>>(OFF_XS, OFF_Y, f_ln_g + l * D_MODEL, f_ln_b + l * D_MODEL,
                                  D_MODEL, D_MODEL);
        launch_gemm(5, OFF_Y, w1, f_b1 + l * DFF, OFF_FFN, MROWS, DFF, D_MODEL);
        launch_gemm(3, OFF_FFN, w2, f_b2 + l * D_MODEL, OFF_XS, MROWS, D_MODEL, DFF);
    }

    final_out<<<BATCH * TOKENS, 256>>>((float*)d_out);
}

// round 3
// speedup vs baseline: 1.6117x; 1.6117x over previous
#include <cuda_runtime.h>
#include <cstdint>
#include <math.h>

// ---------------- problem constants ----------------
#define D_MODEL 1024
#define HEADS   8
#define DH      128
#define DEPTH   2
#define BATCH   2
#define TOKENS  2048
#define GRP     128
#define NGRP    16
#define SEQ     2064
#define MROWS   (BATCH*SEQ)    // 4128
#define DFF     4096

// ---------------- scratch (floats) ----------------
#define OFF_XS    0L
#define SZ_XS     ((long)MROWS*D_MODEL)
#define OFF_Y     (OFF_XS + SZ_XS)
#define SZ_Y      ((long)MROWS*D_MODEL)
#define OFF_QKV   (OFF_Y + SZ_Y)
#define SZ_QKV    ((long)MROWS*3*D_MODEL)
#define OFF_ATT   (OFF_QKV + SZ_QKV)
#define SZ_ATT    ((long)MROWS*D_MODEL)
#define OFF_FFN   (OFF_ATT + SZ_ATT)
#define SZ_FFN    ((long)MROWS*DFF)
#define OFF_RLN   (OFF_FFN + SZ_FFN)
#define SZ_RLN    (32L*D_MODEL)
#define OFF_RQKV  (OFF_RLN + SZ_RLN)
#define SZ_RQKV   (32L*3*D_MODEL)
#define OFF_RATT  (OFF_RQKV + SZ_RQKV)
#define SZ_RATT   (32L*D_MODEL)
#define OFF_RPRJ  (OFF_RATT + SZ_RATT)
#define SZ_RPRJ   (32L*D_MODEL)
#define SCRATCH_FLOATS (OFF_RPRJ + SZ_RPRJ)

__device__ float g_scratch[SCRATCH_FLOATS];

// ---------------- tf32 helpers ----------------
__device__ __forceinline__ uint32_t f2tf32(float x) {
    uint32_t r;
    asm("cvt.rna.tf32.f32 %0, %1;" : "=r"(r) : "f"(x));
    return r;
}

__device__ __forceinline__ void mma_tf32(float& d0, float& d1, float& d2, float& d3,
                                         uint32_t a0, uint32_t a1, uint32_t a2, uint32_t a3,
                                         uint32_t b0, uint32_t b1)
{
    asm volatile("mma.sync.aligned.m16n8k8.row.col.f32.tf32.tf32.f32 "
                 "{%0,%1,%2,%3}, {%4,%5,%6,%7}, {%8,%9}, {%0,%1,%2,%3};\n"
                 : "+f"(d0), "+f"(d1), "+f"(d2), "+f"(d3)
                 : "r"(a0), "r"(a1), "r"(a2), "r"(a3), "r"(b0), "r"(b1));
}

// ---------------- tf32 tensor-core GEMM ----------------
// C = A(MxK) @ B(KxN), row-major. EP bits: 1=+bias, 2=residual-accumulate, 4=leaky_relu
// Block 128x128, BK=16 double-buffered, 8 warps (2x4), warp tile 64x32.
#define GSA 20    // As row stride (floats): banks (l>>2)*20+(l&3) -> conflict-free
#define GSB 132   // Bs row stride: banks (l&3)*132+(l>>2) -> conflict-free

template<int EP>
__global__ __launch_bounds__(256)
void gemm_tf32(long a_off, const float* __restrict__ B,
               const float* __restrict__ bias, long c_off,
               int M, int N, int K)
{
    const float* __restrict__ A = g_scratch + a_off;
    float* __restrict__ C = g_scratch + c_off;

    __shared__ uint32_t As[2][128 * GSA];
    __shared__ uint32_t Bs[2][16 * GSB];

    const int tid = threadIdx.x;
    const int lane = tid & 31;
    const int wid = tid >> 5;
    const int warp_m = wid >> 2;        // 0..1
    const int warp_n = wid & 3;         // 0..3
    const int g  = lane >> 2;           // groupID
    const int tg = lane & 3;            // threadID_in_group
    const int bm = blockIdx.y * 128;
    const int bn = blockIdx.x * 128;

    // staging assignments (2 float4 each for A and B per slab)
    // A: 128 rows x 16 k = 512 float4 ; B: 16 k x 128 n = 512 float4
    int a_row[2], a_c4[2], b_k[2], b_c4[2];
    #pragma unroll
    for (int it = 0; it < 2; it++) {
        int f = tid + it * 256;
        a_row[it] = f >> 2;  a_c4[it] = (f & 3) * 4;
        b_k[it]   = f >> 5;  b_c4[it] = (f & 31) * 4;
    }
    int a_grow[2];
    #pragma unroll
    for (int it = 0; it < 2; it++) {
        int r = bm + a_row[it];
        a_grow[it] = (r < M) ? r : (M - 1);
    }

    float acc[4][4][4];
    #pragma unroll
    for (int mi = 0; mi < 4; mi++)
        #pragma unroll
        for (int ni = 0; ni < 4; ni++)
            #pragma unroll
            for (int q = 0; q < 4; q++) acc[mi][ni][q] = 0.f;

    const int nk = K / 16;
    float4 aR[2], bR[2];

    // prologue: slab 0
    #pragma unroll
    for (int it = 0; it < 2; it++) {
        aR[it] = *reinterpret_cast<const float4*>(A + (size_t)a_grow[it] * K + a_c4[it]);
        bR[it] = *reinterpret_cast<const float4*>(B + (size_t)b_k[it] * N + bn + b_c4[it]);
    }
    #pragma unroll
    for (int it = 0; it < 2; it++) {
        uint4 ua = make_uint4(f2tf32(aR[it].x), f2tf32(aR[it].y), f2tf32(aR[it].z), f2tf32(aR[it].w));
        *reinterpret_cast<uint4*>(&As[0][a_row[it] * GSA + a_c4[it]]) = ua;
        uint4 ub = make_uint4(f2tf32(bR[it].x), f2tf32(bR[it].y), f2tf32(bR[it].z), f2tf32(bR[it].w));
        *reinterpret_cast<uint4*>(&Bs[0][b_k[it] * GSB + b_c4[it]]) = ub;
    }
    __syncthreads();

    for (int s = 0; s < nk; s++) {
        const int cur = s & 1;
        if (s + 1 < nk) {
            const int k0 = (s + 1) * 16;
            #pragma unroll
            for (int it = 0; it < 2; it++) {
                aR[it] = *reinterpret_cast<const float4*>(A + (size_t)a_grow[it] * K + k0 + a_c4[it]);
                bR[it] = *reinterpret_cast<const float4*>(B + (size_t)(k0 + b_k[it]) * N + bn + b_c4[it]);
            }
        }

        const uint32_t* __restrict__ as = As[cur];
        const uint32_t* __restrict__ bs = Bs[cur];
        #pragma unroll
        for (int ks = 0; ks < 2; ks++) {
            const int kc = ks * 8;
            uint32_t a[4][4], b[4][2];
            #pragma unroll
            for (int mi = 0; mi < 4; mi++) {
                int r = warp_m * 64 + mi * 16 + g;
                a[mi][0] = as[r * GSA + kc + tg];
                a[mi][1] = as[(r + 8) * GSA + kc + tg];
                a[mi][2] = as[r * GSA + kc + tg + 4];
                a[mi][3] = as[(r + 8) * GSA + kc + tg + 4];
            }
            #pragma unroll
            for (int ni = 0; ni < 4; ni++) {
                int c = warp_n * 32 + ni * 8 + g;
                b[ni][0] = bs[(kc + tg) * GSB + c];
                b[ni][1] = bs[(kc + tg + 4) * GSB + c];
            }
            #pragma unroll
            for (int mi = 0; mi < 4; mi++)
                #pragma unroll
                for (int ni = 0; ni < 4; ni++)
                    mma_tf32(acc[mi][ni][0], acc[mi][ni][1], acc[mi][ni][2], acc[mi][ni][3],
                             a[mi][0], a[mi][1], a[mi][2], a[mi][3], b[ni][0], b[ni][1]);
        }

        if (s + 1 < nk) {
            const int nxt = (s + 1) & 1;
            #pragma unroll
            for (int it = 0; it < 2; it++) {
                uint4 ua = make_uint4(f2tf32(aR[it].x), f2tf32(aR[it].y), f2tf32(aR[it].z), f2tf32(aR[it].w));
                *reinterpret_cast<uint4*>(&As[nxt][a_row[it] * GSA + a_c4[it]]) = ua;
                uint4 ub = make_uint4(f2tf32(bR[it].x), f2tf32(bR[it].y), f2tf32(bR[it].z), f2tf32(bR[it].w));
                *reinterpret_cast<uint4*>(&Bs[nxt][b_k[it] * GSB + b_c4[it]]) = ub;
            }
        }
        __syncthreads();
    }

    // epilogue
    #pragma unroll
    for (int mi = 0; mi < 4; mi++) {
        #pragma unroll
        for (int half = 0; half < 2; half++) {
            const int r = bm + warp_m * 64 + mi * 16 + g + half * 8;
            if (r >= M) continue;
            #pragma unroll
            for (int ni = 0; ni < 4; ni++) {
                float v0 = acc[mi][ni][half * 2 + 0];
                float v1 = acc[mi][ni][half * 2 + 1];
                const int c = bn + warp_n * 32 + ni * 8 + tg * 2;
                float* cp = C + (size_t)r * N + c;
                if (EP & 1) { v0 += bias[c]; v1 += bias[c + 1]; }
                if (EP & 4) {
                    v0 = v0 > 0.f ? v0 : 0.01f * v0;
                    v1 = v1 > 0.f ? v1 : 0.01f * v1;
                }
                if (EP & 2) {
                    float2 old = *reinterpret_cast<float2*>(cp);
                    v0 += old.x; v1 += old.y;
                }
                *reinterpret_cast<float2*>(cp) = make_float2(v0, v1);
            }
        }
    }
}

// ---------------- LayerNorm (row length 1024), strided ----------------
__global__ __launch_bounds__(256)
void ln_kernel(long in_off, long out_off,
               const float* __restrict__ gamma, const float* __restrict__ beta,
               long in_stride, long out_stride)
{
    const float* __restrict__ in = g_scratch + in_off;
    float* __restrict__ out = g_scratch + out_off;

    const int row = blockIdx.x;
    const int tid = threadIdx.x;
    const float4 v = reinterpret_cast<const float4*>(in + (size_t)row * in_stride)[tid];

    float s  = v.x + v.y + v.z + v.w;
    float sq = v.x*v.x + v.y*v.y + v.z*v.z + v.w*v.w;
    #pragma unroll
    for (int o = 16; o > 0; o >>= 1) {
        s  += __shfl_xor_sync(0xffffffffu, s,  o);
        sq += __shfl_xor_sync(0xffffffffu, sq, o);
    }
    __shared__ float ss[8], sqs[8];
    const int warp = tid >> 5;
    if ((tid & 31) == 0) { ss[warp] = s; sqs[warp] = sq; }
    __syncthreads();
    float ts = 0.f, tq = 0.f;
    #pragma unroll
    for (int w = 0; w < 8; w++) { ts += ss[w]; tq += sqs[w]; }
    const float mean = ts * (1.0f / D_MODEL);
    const float var  = tq * (1.0f / D_MODEL) - mean * mean;
    const float rstd = rsqrtf(var + 1e-5f);

    const float4 g4 = reinterpret_cast<const float4*>(gamma)[tid];
    const float4 b4 = reinterpret_cast<const float4*>(beta)[tid];
    float4 o;
    o.x = (v.x - mean) * rstd * g4.x + b4.x;
    o.y = (v.y - mean) * rstd * g4.y + b4.y;
    o.z = (v.z - mean) * rstd * g4.z + b4.z;
    o.w = (v.w - mean) * rstd * g4.w + b4.w;
    reinterpret_cast<float4*>(out + (size_t)row * out_stride)[tid] = o;
}

// ---------------- flash attention (unscaled dots!), dh=128 ---------------
#define FA_BR 32
#define FA_BC 32
#define FA_PAD 132

__global__ __launch_bounds__(256)
void flash_attn(long qkv_off, long out_off, int S)
{
    __shared__ float Qs[FA_BR][FA_PAD];
    __shared__ float KVs[FA_BC][FA_PAD];

    const float* __restrict__ qkv = g_scratch + qkv_off;
    float* __restrict__ out = g_scratch + out_off;

    const int b = blockIdx.z, h = blockIdx.y;
    const int q0 = blockIdx.x * FA_BR;
    const int tid = threadIdx.x;
    const int tx = tid & 31;
    const int ty = tid >> 5;
    const float* base = qkv + (size_t)b * S * (3 * D_MODEL);

    #pragma unroll
    for (int it = 0; it < 4; it++) {
        int idx = it * 256 + tid;
        int r = idx >> 5, c4 = (idx & 31) * 4;
        int qr = q0 + r; if (qr >= S) qr = S - 1;
        *reinterpret_cast<float4*>(&Qs[r][c4]) =
            *reinterpret_cast<const float4*>(base + (size_t)qr * (3*D_MODEL) + h * DH + c4);
    }

    float m_run[4], l_run[4], acc[4][4];
    #pragma unroll
    for (int i = 0; i < 4; i++) {
        m_run[i] = -1e30f; l_run[i] = 0.f;
        #pragma unroll
        for (int j = 0; j < 4; j++) acc[i][j] = 0.f;
    }

    for (int kt0 = 0; kt0 < S; kt0 += FA_BC) {
        __syncthreads();
        #pragma unroll
        for (int it = 0; it < 4; it++) {
            int idx = it * 256 + tid;
            int r = idx >> 5, c4 = (idx & 31) * 4;
            int kr = kt0 + r; if (kr >= S) kr = S - 1;
            *reinterpret_cast<float4*>(&KVs[r][c4]) =
                *reinterpret_cast<const float4*>(base + (size_t)kr * (3*D_MODEL) + D_MODEL + h * DH + c4);
        }
        __syncthreads();

        float sv[4] = {0.f, 0.f, 0.f, 0.f};
        #pragma unroll 4
        for (int d = 0; d < DH; d += 4) {
            float4 kv = *reinterpret_cast<float4*>(&KVs[tx][d]);
            #pragma unroll
            for (int i = 0; i < 4; i++) {
                float4 qv = *reinterpret_cast<float4*>(&Qs[ty * 4 + i][d]);
                sv[i] += qv.x*kv.x + qv.y*kv.y + qv.z*kv.z + qv.w*kv.w;
            }
        }

        const bool valid = (kt0 + tx) < S;
        float p_reg[4];
        #pragma unroll
        for (int i = 0; i < 4; i++) {
            float s = valid ? sv[i] : -1e30f;
            float mx = s;
            #pragma unroll
            for (int o = 16; o > 0; o >>= 1)
                mx = fmaxf(mx, __shfl_xor_sync(0xffffffffu, mx, o));
            const float mnew = fmaxf(m_run[i], mx);
            const float scale = __expf(m_run[i] - mnew);
            float p = __expf(s - mnew);
            float rs = p;
            #pragma unroll
            for (int o = 16; o > 0; o >>= 1)
                rs += __shfl_xor_sync(0xffffffffu, rs, o);
            l_run[i] = l_run[i] * scale + rs;
            m_run[i] = mnew;
            #pragma unroll
            for (int j = 0; j < 4; j++) acc[i][j] *= scale;
            p_reg[i] = p;
        }

        __syncthreads();
        #pragma unroll
        for (int it = 0; it < 4; it++) {
            int idx = it * 256 + tid;
            int r = idx >> 5, c4 = (idx & 31) * 4;
            int kr = kt0 + r; if (kr >= S) kr = S - 1;
            *reinterpret_cast<float4*>(&KVs[r][c4]) =
                *reinterpret_cast<const float4*>(base + (size_t)kr * (3*D_MODEL) + 2 * D_MODEL + h * DH + c4);
        }
        __syncthreads();

        #pragma unroll 8
        for (int k = 0; k < FA_BC; k++) {
            float4 vv = *reinterpret_cast<float4*>(&KVs[k][tx * 4]);
            #pragma unroll
            for (int i = 0; i < 4; i++) {
                float p = __shfl_sync(0xffffffffu, p_reg[i], k);
                acc[i][0] += p * vv.x; acc[i][1] += p * vv.y;
                acc[i][2] += p * vv.z; acc[i][3] += p * vv.w;
            }
        }
    }

    #pragma unroll
    for (int i = 0; i < 4; i++) {
        int row = q0 + ty * 4 + i;
        if (row >= S) continue;
        float inv_l = 1.0f / l_run[i];
        float4 o = make_float4(acc[i][0]*inv_l, acc[i][1]*inv_l,
                               acc[i][2]*inv_l, acc[i][3]*inv_l);
        *reinterpret_cast<float4*>(out + (size_t)(b * S + row) * D_MODEL + h * DH + tx * 4) = o;
    }
}

// ---------------- relay attention (16 tokens) ----------------
__global__ __launch_bounds__(128)
void relay_attn(long rqkv_off, long ratt_off)
{
    const float* __restrict__ rqkv = g_scratch + rqkv_off;
    float* __restrict__ rattn = g_scratch + ratt_off;

    const int h = blockIdx.x, b = blockIdx.y;
    __shared__ float q[16][128], k[16][128], v[16][128];
    __shared__ float p[16][16];
    const int tid = threadIdx.x;

    #pragma unroll
    for (int it = 0; it < 4; it++) {
        int idx4 = it * 128 + tid;
        int r = idx4 >> 5, c = (idx4 & 31) * 4;
        const float* rowp = rqkv + (size_t)(b * 16 + r) * (3 * D_MODEL);
        *reinterpret_cast<float4*>(&q[r][c]) = *reinterpret_cast<const float4*>(rowp + h * DH + c);
        *reinterpret_cast<float4*>(&k[r][c]) = *reinterpret_cast<const float4*>(rowp + D_MODEL + h * DH + c);
        *reinterpret_cast<float4*>(&v[r][c]) = *reinterpret_cast<const float4*>(rowp + 2 * D_MODEL + h * DH + c);
    }
    __syncthreads();

    #pragma unroll
    for (int t = 0; t < 2; t++) {
        int ij = tid * 2 + t;
        int i = ij >> 4, j = ij & 15;
        float s = 0.f;
        for (int d = 0; d < 128; d += 4) {
            float4 qa = *reinterpret_cast<float4*>(&q[i][d]);
            float4 ka = *reinterpret_cast<float4*>(&k[j][d]);
            s += qa.x*ka.x + qa.y*ka.y + qa.z*ka.z + qa.w*ka.w;
        }
        p[i][j] = s;
    }
    __syncthreads();

    if (tid < 16) {
        float mx = -1e30f;
        #pragma unroll
        for (int j = 0; j < 16; j++) mx = fmaxf(mx, p[tid][j]);
        float sum = 0.f; float e[16];
        #pragma unroll
        for (int j = 0; j < 16; j++) { e[j] = __expf(p[tid][j] - mx); sum += e[j]; }
        float inv = 1.0f / sum;
        #pragma unroll
        for (int j = 0; j < 16; j++) p[tid][j] = e[j] * inv;
    }
    __syncthreads();

    const int i = tid >> 3, c0 = (tid & 7) * 16;
    #pragma unroll
    for (int c = 0; c < 16; c++) {
        float o = 0.f;
        #pragma unroll
        for (int j = 0; j < 16; j++) o += p[i][j] * v[j][c0 + c];
        rattn[(size_t)(b * 16 + i) * D_MODEL + h * DH + c0 + c] = o;
    }
}

// ---------------- small glue kernels ----------------
__global__ void init_xs(const float* __restrict__ x, const float* __restrict__ relay_emb)
{
    float* __restrict__ xs = g_scratch + OFF_XS;
    const int row = blockIdx.x;
    const int b = row / SEQ, sr = row % SEQ;
    const int grp = sr / (GRP + 1), w = sr % (GRP + 1);
    float4 val;
    if (w == 0)
        val = reinterpret_cast<const float4*>(relay_emb)[threadIdx.x];
    else {
        int t = grp * GRP + (w - 1);
        val = reinterpret_cast<const float4*>(x + (size_t)(b * TOKENS + t) * D_MODEL)[threadIdx.x];
    }
    reinterpret_cast<float4*>(xs + (size_t)row * D_MODEL)[threadIdx.x] = val;
}

__global__ void relay_scatter(long rprj_off, const float* __restrict__ bias)
{
    const float* __restrict__ rproj = g_scratch + rprj_off;
    float* __restrict__ xs = g_scratch + OFF_XS;
    const int row = blockIdx.x;
    float4 r = reinterpret_cast<const float4*>(rproj + (size_t)row * D_MODEL)[threadIdx.x];
    float4 bb = reinterpret_cast<const float4*>(bias)[threadIdx.x];
    float4* dst = reinterpret_cast<float4*>(xs + (size_t)row * (GRP + 1) * D_MODEL) + threadIdx.x;
    float4 c = *dst;
    c.x += r.x + bb.x; c.y += r.y + bb.y; c.z += r.z + bb.z; c.w += r.w + bb.w;
    *dst = c;
}

__global__ void final_out(float* __restrict__ out)
{
    const float* __restrict__ xs = g_scratch + OFF_XS;
    const int row = blockIdx.x;
    const int b = row / TOKENS, t = row % TOKENS;
    const int src = b * SEQ + (t >> 7) * (GRP + 1) + 1 + (t & 127);
    reinterpret_cast<float4*>(out + (size_t)row * D_MODEL)[threadIdx.x] =
        reinterpret_cast<const float4*>(xs + (size_t)src * D_MODEL)[threadIdx.x];
}

// ---------------- host side ----------------
static void launch_gemm(int ep, long a_off, const float* B, const float* bias,
                        long c_off, int M, int N, int K)
{
    dim3 grid(N / 128, (M + 127) / 128);
    switch (ep) {
        case 0: gemm_tf32<0><<<grid, 256>>>(a_off, B, bias, c_off, M, N, K); break;
        case 3: gemm_tf32<3><<<grid, 256>>>(a_off, B, bias, c_off, M, N, K); break;
        case 5: gemm_tf32<5><<<grid, 256>>>(a_off, B, bias, c_off, M, N, K); break;
    }
}

extern "C" void kernel_launch(void* const* d_in, const int* in_sizes, int n_in,
                              void* d_out, int out_size)
{
    const float* x         = (const float*)d_in[0];
    const float* relay_emb = (const float*)d_in[1];
    const float* r_ln_g    = (const float*)d_in[2];
    const float* r_ln_b    = (const float*)d_in[3];
    const float* r_qkv     = (const float*)d_in[4];
    const float* r_ow      = (const float*)d_in[5];
    const float* r_ob      = (const float*)d_in[6];
    const float* l_ln_g    = (const float*)d_in[7];
    const float* l_ln_b    = (const float*)d_in[8];
    const float* l_qkv     = (const float*)d_in[9];
    const float* l_ow      = (const float*)d_in[10];
    const float* l_ob      = (const float*)d_in[11];
    const float* f_ln_g    = (const float*)d_in[12];
    const float* f_ln_b    = (const float*)d_in[13];
    const float* f_w1      = (const float*)d_in[14];
    const float* f_b1      = (const float*)d_in[15];
    const float* f_w2      = (const float*)d_in[16];
    const float* f_b2      = (const float*)d_in[17];

    init_xs<<<MROWS, 256>>>(x, relay_emb);

    for (int l = 0; l < DEPTH; l++) {
        const float* rqkv_w = r_qkv + (size_t)l * D_MODEL * 3 * D_MODEL;
        const float* row_w  = r_ow  + (size_t)l * D_MODEL * D_MODEL;
        const float* lqkv_w = l_qkv + (size_t)l * D_MODEL * 3 * D_MODEL;
        const float* low_w  = l_ow  + (size_t)l * D_MODEL * D_MODEL;
        const float* w1     = f_w1  + (size_t)l * D_MODEL * DFF;
        const float* w2     = f_w2  + (size_t)l * DFF * D_MODEL;

        // ---- relay attention over the 16 relay tokens per batch ----
        ln_kernel<<<32, 256>>>(OFF_XS, OFF_RLN, r_ln_g + l * D_MODEL, r_ln_b + l * D_MODEL,
                               (long)(GRP + 1) * D_MODEL, D_MODEL);
        launch_gemm(0, OFF_RLN, rqkv_w, nullptr, OFF_RQKV, 32, 3 * D_MODEL, D_MODEL);
        relay_attn<<<dim3(HEADS, BATCH), 128>>>(OFF_RQKV, OFF_RATT);
        launch_gemm(0, OFF_RATT, row_w, nullptr, OFF_RPRJ, 32, D_MODEL, D_MODEL);
        relay_scatter<<<32, 256>>>(OFF_RPRJ, r_ob + l * D_MODEL);

        // ---- full attention over stitched sequence ----
        ln_kernel<<<MROWS, 256>>>(OFF_XS, OFF_Y, l_ln_g + l * D_MODEL, l_ln_b + l * D_MODEL,
                                  D_MODEL, D_MODEL);
        launch_gemm(0, OFF_Y, lqkv_w, nullptr, OFF_QKV, MROWS, 3 * D_MODEL, D_MODEL);
        flash_attn<<<dim3((SEQ + FA_BR - 1) / FA_BR, HEADS, BATCH), 256>>>(OFF_QKV, OFF_ATT, SEQ);
        launch_gemm(3, OFF_ATT, low_w, l_ob + l * D_MODEL, OFF_XS, MROWS, D_MODEL, D_MODEL);

        // ---- FFN ----
        ln_kernel<<<MROWS, 256>>>(OFF_XS, OFF_Y, f_ln_g + l * D_MODEL, f_ln_b + l * D_MODEL,
                                  D_MODEL, D_MODEL);
        launch_gemm(5, OFF_Y, w1, f_b1 + l * DFF, OFF_FFN, MROWS, DFF, D_MODEL);
        launch_gemm(3, OFF_FFN, w2, f_b2 + l * D_MODEL, OFF_XS, MROWS, D_MODEL, DFF);
    }

    final_out<<<BATCH * TOKENS, 256>>>((float*)d_out);
}

// round 5
// speedup vs baseline: 2.6431x; 1.6399x over previous
#include <cuda_runtime.h>
#include <cstdint>
#include <math.h>

// ---------------- problem constants ----------------
#define D_MODEL 1024
#define HEADS   8
#define DH      128
#define DEPTH   2
#define BATCH   2
#define TOKENS  2048
#define GRP     128
#define NGRP    16
#define SEQ     2064
#define MROWS   (BATCH*SEQ)    // 4128
#define DFF     4096

// ---------------- scratch (floats) ----------------
#define OFF_XS    0L
#define SZ_XS     ((long)MROWS*D_MODEL)
#define OFF_Y     (OFF_XS + SZ_XS)
#define SZ_Y      ((long)MROWS*D_MODEL)
#define OFF_QKV   (OFF_Y + SZ_Y)
#define SZ_QKV    ((long)MROWS*3*D_MODEL)
#define OFF_ATT   (OFF_QKV + SZ_QKV)
#define SZ_ATT    ((long)MROWS*D_MODEL)
#define OFF_FFN   (OFF_ATT + SZ_ATT)
#define SZ_FFN    ((long)MROWS*DFF)
#define OFF_RLN   (OFF_FFN + SZ_FFN)
#define SZ_RLN    (32L*D_MODEL)
#define OFF_RQKV  (OFF_RLN + SZ_RLN)
#define SZ_RQKV   (32L*3*D_MODEL)
#define OFF_RATT  (OFF_RQKV + SZ_RQKV)
#define SZ_RATT   (32L*D_MODEL)
#define OFF_RPRJ  (OFF_RATT + SZ_RATT)
#define SZ_RPRJ   (32L*D_MODEL)
#define SCRATCH_FLOATS (OFF_RPRJ + SZ_RPRJ)

__device__ float g_scratch[SCRATCH_FLOATS];

// ---------------- tf32 helpers ----------------
__device__ __forceinline__ uint32_t f2tf32(float x) {
    uint32_t r;
    asm("cvt.rna.tf32.f32 %0, %1;" : "=r"(r) : "f"(x));
    return r;
}

__device__ __forceinline__ void mma_tf32(float& d0, float& d1, float& d2, float& d3,
                                         uint32_t a0, uint32_t a1, uint32_t a2, uint32_t a3,
                                         uint32_t b0, uint32_t b1)
{
    asm volatile("mma.sync.aligned.m16n8k8.row.col.f32.tf32.tf32.f32 "
                 "{%0,%1,%2,%3}, {%4,%5,%6,%7}, {%8,%9}, {%0,%1,%2,%3};\n"
                 : "+f"(d0), "+f"(d1), "+f"(d2), "+f"(d3)
                 : "r"(a0), "r"(a1), "r"(a2), "r"(a3), "r"(b0), "r"(b1));
}

// ---------------- tf32 tensor-core GEMM ----------------
// C = A(MxK) @ B(KxN), row-major. EP bits: 1=+bias, 2=residual-accumulate, 4=leaky_relu
#define GSA 20
#define GSB 132

template<int EP>
__global__ __launch_bounds__(256)
void gemm_tf32(long a_off, const float* __restrict__ B,
               const float* __restrict__ bias, long c_off,
               int M, int N, int K)
{
    const float* __restrict__ A = g_scratch + a_off;
    float* __restrict__ C = g_scratch + c_off;

    __shared__ uint32_t As[2][128 * GSA];
    __shared__ uint32_t Bs[2][16 * GSB];

    const int tid = threadIdx.x;
    const int lane = tid & 31;
    const int wid = tid >> 5;
    const int warp_m = wid >> 2;
    const int warp_n = wid & 3;
    const int g  = lane >> 2;
    const int tg = lane & 3;
    const int bm = blockIdx.y * 128;
    const int bn = blockIdx.x * 128;

    int a_row[2], a_c4[2], b_k[2], b_c4[2];
    #pragma unroll
    for (int it = 0; it < 2; it++) {
        int f = tid + it * 256;
        a_row[it] = f >> 2;  a_c4[it] = (f & 3) * 4;
        b_k[it]   = f >> 5;  b_c4[it] = (f & 31) * 4;
    }
    int a_grow[2];
    #pragma unroll
    for (int it = 0; it < 2; it++) {
        int r = bm + a_row[it];
        a_grow[it] = (r < M) ? r : (M - 1);
    }

    float acc[4][4][4];
    #pragma unroll
    for (int mi = 0; mi < 4; mi++)
        #pragma unroll
        for (int ni = 0; ni < 4; ni++)
            #pragma unroll
            for (int q = 0; q < 4; q++) acc[mi][ni][q] = 0.f;

    const int nk = K / 16;
    float4 aR[2], bR[2];

    #pragma unroll
    for (int it = 0; it < 2; it++) {
        aR[it] = *reinterpret_cast<const float4*>(A + (size_t)a_grow[it] * K + a_c4[it]);
        bR[it] = *reinterpret_cast<const float4*>(B + (size_t)b_k[it] * N + bn + b_c4[it]);
    }
    #pragma unroll
    for (int it = 0; it < 2; it++) {
        uint4 ua = make_uint4(f2tf32(aR[it].x), f2tf32(aR[it].y), f2tf32(aR[it].z), f2tf32(aR[it].w));
        *reinterpret_cast<uint4*>(&As[0][a_row[it] * GSA + a_c4[it]]) = ua;
        uint4 ub = make_uint4(f2tf32(bR[it].x), f2tf32(bR[it].y), f2tf32(bR[it].z), f2tf32(bR[it].w));
        *reinterpret_cast<uint4*>(&Bs[0][b_k[it] * GSB + b_c4[it]]) = ub;
    }
    __syncthreads();

    for (int s = 0; s < nk; s++) {
        const int cur = s & 1;
        if (s + 1 < nk) {
            const int k0 = (s + 1) * 16;
            #pragma unroll
            for (int it = 0; it < 2; it++) {
                aR[it] = *reinterpret_cast<const float4*>(A + (size_t)a_grow[it] * K + k0 + a_c4[it]);
                bR[it] = *reinterpret_cast<const float4*>(B + (size_t)(k0 + b_k[it]) * N + bn + b_c4[it]);
            }
        }

        const uint32_t* __restrict__ as = As[cur];
        const uint32_t* __restrict__ bs = Bs[cur];
        #pragma unroll
        for (int ks = 0; ks < 2; ks++) {
            const int kc = ks * 8;
            uint32_t a[4][4], b[4][2];
            #pragma unroll
            for (int mi = 0; mi < 4; mi++) {
                int r = warp_m * 64 + mi * 16 + g;
                a[mi][0] = as[r * GSA + kc + tg];
                a[mi][1] = as[(r + 8) * GSA + kc + tg];
                a[mi][2] = as[r * GSA + kc + tg + 4];
                a[mi][3] = as[(r + 8) * GSA + kc + tg + 4];
            }
            #pragma unroll
            for (int ni = 0; ni < 4; ni++) {
                int c = warp_n * 32 + ni * 8 + g;
                b[ni][0] = bs[(kc + tg) * GSB + c];
                b[ni][1] = bs[(kc + tg + 4) * GSB + c];
            }
            #pragma unroll
            for (int mi = 0; mi < 4; mi++)
                #pragma unroll
                for (int ni = 0; ni < 4; ni++)
                    mma_tf32(acc[mi][ni][0], acc[mi][ni][1], acc[mi][ni][2], acc[mi][ni][3],
                             a[mi][0], a[mi][1], a[mi][2], a[mi][3], b[ni][0], b[ni][1]);
        }

        if (s + 1 < nk) {
            const int nxt = (s + 1) & 1;
            #pragma unroll
            for (int it = 0; it < 2; it++) {
                uint4 ua = make_uint4(f2tf32(aR[it].x), f2tf32(aR[it].y), f2tf32(aR[it].z), f2tf32(aR[it].w));
                *reinterpret_cast<uint4*>(&As[nxt][a_row[it] * GSA + a_c4[it]]) = ua;
                uint4 ub = make_uint4(f2tf32(bR[it].x), f2tf32(bR[it].y), f2tf32(bR[it].z), f2tf32(bR[it].w));
                *reinterpret_cast<uint4*>(&Bs[nxt][b_k[it] * GSB + b_c4[it]]) = ub;
            }
        }
        __syncthreads();
    }

    #pragma unroll
    for (int mi = 0; mi < 4; mi++) {
        #pragma unroll
        for (int half = 0; half < 2; half++) {
            const int r = bm + warp_m * 64 + mi * 16 + g + half * 8;
            if (r >= M) continue;
            #pragma unroll
            for (int ni = 0; ni < 4; ni++) {
                float v0 = acc[mi][ni][half * 2 + 0];
                float v1 = acc[mi][ni][half * 2 + 1];
                const int c = bn + warp_n * 32 + ni * 8 + tg * 2;
                float* cp = C + (size_t)r * N + c;
                if (EP & 1) { v0 += bias[c]; v1 += bias[c + 1]; }
                if (EP & 4) {
                    v0 = v0 > 0.f ? v0 : 0.01f * v0;
                    v1 = v1 > 0.f ? v1 : 0.01f * v1;
                }
                if (EP & 2) {
                    float2 old = *reinterpret_cast<float2*>(cp);
                    v0 += old.x; v1 += old.y;
                }
                *reinterpret_cast<float2*>(cp) = make_float2(v0, v1);
            }
        }
    }
}

// ---------------- LayerNorm (row length 1024), strided ----------------
__global__ __launch_bounds__(256)
void ln_kernel(long in_off, long out_off,
               const float* __restrict__ gamma, const float* __restrict__ beta,
               long in_stride, long out_stride)
{
    const float* __restrict__ in = g_scratch + in_off;
    float* __restrict__ out = g_scratch + out_off;

    const int row = blockIdx.x;
    const int tid = threadIdx.x;
    const float4 v = reinterpret_cast<const float4*>(in + (size_t)row * in_stride)[tid];

    float s  = v.x + v.y + v.z + v.w;
    float sq = v.x*v.x + v.y*v.y + v.z*v.z + v.w*v.w;
    #pragma unroll
    for (int o = 16; o > 0; o >>= 1) {
        s  += __shfl_xor_sync(0xffffffffu, s,  o);
        sq += __shfl_xor_sync(0xffffffffu, sq, o);
    }
    __shared__ float ss[8], sqs[8];
    const int warp = tid >> 5;
    if ((tid & 31) == 0) { ss[warp] = s; sqs[warp] = sq; }
    __syncthreads();
    float ts = 0.f, tq = 0.f;
    #pragma unroll
    for (int w = 0; w < 8; w++) { ts += ss[w]; tq += sqs[w]; }
    const float mean = ts * (1.0f / D_MODEL);
    const float var  = tq * (1.0f / D_MODEL) - mean * mean;
    const float rstd = rsqrtf(var + 1e-5f);

    const float4 g4 = reinterpret_cast<const float4*>(gamma)[tid];
    const float4 b4 = reinterpret_cast<const float4*>(beta)[tid];
    float4 o;
    o.x = (v.x - mean) * rstd * g4.x + b4.x;
    o.y = (v.y - mean) * rstd * g4.y + b4.y;
    o.z = (v.z - mean) * rstd * g4.z + b4.z;
    o.w = (v.w - mean) * rstd * g4.w + b4.w;
    reinterpret_cast<float4*>(out + (size_t)row * out_stride)[tid] = o;
}

// ---------------- tf32 mma flash attention (unscaled dots!) ----------------
// Br=64 q rows/block, Bc=64 kv/tile, 4 warps; each warp owns 16 full rows.
// K phase smem stride 132, V phase stride 136 (both conflict-free for frag LDS).
__global__ __launch_bounds__(128)
void flash_attn_mma(long qkv_off, long out_off, int S)
{
    __shared__ uint32_t KV[64 * 136];

    const float* __restrict__ qkv = g_scratch + qkv_off;
    float* __restrict__ out = g_scratch + out_off;

    const int b = blockIdx.z, h = blockIdx.y;
    const int q0 = blockIdx.x * 64;
    const int tid = threadIdx.x;
    const int lane = tid & 31, wid = tid >> 5;
    const int g = lane >> 2, tg = lane & 3;
    const float* base = qkv + (size_t)b * S * (3 * D_MODEL);

    // ---- stage Q tile (tf32) then lift to A-fragments in registers ----
    #pragma unroll
    for (int it = 0; it < 16; it++) {
        int idx = it * 128 + tid;
        int r = idx >> 5, c4 = (idx & 31) * 4;
        int qr = q0 + r; if (qr >= S) qr = S - 1;
        float4 v = *reinterpret_cast<const float4*>(base + (size_t)qr * (3*D_MODEL) + h * DH + c4);
        uint32_t* p = &KV[r * 132 + c4];
        p[0] = f2tf32(v.x); p[1] = f2tf32(v.y); p[2] = f2tf32(v.z); p[3] = f2tf32(v.w);
    }
    __syncthreads();
    uint32_t qf[16][4];
    {
        const int qrow = wid * 16 + g;
        #pragma unroll
        for (int kc16 = 0; kc16 < 16; kc16++) {
            const int kc = kc16 * 8;
            qf[kc16][0] = KV[qrow * 132 + kc + tg];
            qf[kc16][1] = KV[(qrow + 8) * 132 + kc + tg];
            qf[kc16][2] = KV[qrow * 132 + kc + tg + 4];
            qf[kc16][3] = KV[(qrow + 8) * 132 + kc + tg + 4];
        }
    }

    float o_acc[16][4];
    #pragma unroll
    for (int ni = 0; ni < 16; ni++)
        o_acc[ni][0] = o_acc[ni][1] = o_acc[ni][2] = o_acc[ni][3] = 0.f;
    float m0 = -1e30f, m1 = -1e30f, l0 = 0.f, l1 = 0.f;

    for (int kt = 0; kt < S; kt += 64) {
        __syncthreads();
        // K tile -> smem (tf32), stride 132
        #pragma unroll
        for (int it = 0; it < 16; it++) {
            int idx = it * 128 + tid;
            int r = idx >> 5, c4 = (idx & 31) * 4;
            int kr = kt + r; if (kr >= S) kr = S - 1;
            float4 v = *reinterpret_cast<const float4*>(base + (size_t)kr * (3*D_MODEL) + D_MODEL + h * DH + c4);
            uint32_t* p = &KV[r * 132 + c4];
            p[0] = f2tf32(v.x); p[1] = f2tf32(v.y); p[2] = f2tf32(v.z); p[3] = f2tf32(v.w);
        }
        __syncthreads();

        // S = Q K^T (16x64 per warp)
        float sf[8][4];
        #pragma unroll
        for (int ni = 0; ni < 8; ni++)
            sf[ni][0] = sf[ni][1] = sf[ni][2] = sf[ni][3] = 0.f;
        #pragma unroll
        for (int kc16 = 0; kc16 < 16; kc16++) {
            const int kc = kc16 * 8;
            #pragma unroll
            for (int ni = 0; ni < 8; ni++) {
                uint32_t b0 = KV[(ni * 8 + g) * 132 + kc + tg];
                uint32_t b1 = KV[(ni * 8 + g) * 132 + kc + tg + 4];
                mma_tf32(sf[ni][0], sf[ni][1], sf[ni][2], sf[ni][3],
                         qf[kc16][0], qf[kc16][1], qf[kc16][2], qf[kc16][3], b0, b1);
            }
        }

        // online softmax (rows g and g+8; quad shuffles complete each row)
        float mx0 = -1e30f, mx1 = -1e30f;
        #pragma unroll
        for (int ni = 0; ni < 8; ni++) {
            int c = kt + ni * 8 + tg * 2;
            if (c >= S)     { sf[ni][0] = -1e30f; sf[ni][2] = -1e30f; }
            if (c + 1 >= S) { sf[ni][1] = -1e30f; sf[ni][3] = -1e30f; }
            mx0 = fmaxf(mx0, fmaxf(sf[ni][0], sf[ni][1]));
            mx1 = fmaxf(mx1, fmaxf(sf[ni][2], sf[ni][3]));
        }
        mx0 = fmaxf(mx0, __shfl_xor_sync(0xffffffffu, mx0, 1));
        mx0 = fmaxf(mx0, __shfl_xor_sync(0xffffffffu, mx0, 2));
        mx1 = fmaxf(mx1, __shfl_xor_sync(0xffffffffu, mx1, 1));
        mx1 = fmaxf(mx1, __shfl_xor_sync(0xffffffffu, mx1, 2));
        const float M0 = fmaxf(m0, mx0), M1 = fmaxf(m1, mx1);
        const float sc0 = __expf(m0 - M0), sc1 = __expf(m1 - M1);
        float rs0 = 0.f, rs1 = 0.f;
        uint32_t pf[8][4];
        #pragma unroll
        for (int ni = 0; ni < 8; ni++) {
            float p00 = __expf(sf[ni][0] - M0);
            float p01 = __expf(sf[ni][1] - M0);
            float p10 = __expf(sf[ni][2] - M1);
            float p11 = __expf(sf[ni][3] - M1);
            rs0 += p00 + p01; rs1 += p10 + p11;
            pf[ni][0] = f2tf32(p00); pf[ni][1] = f2tf32(p01);
            pf[ni][2] = f2tf32(p10); pf[ni][3] = f2tf32(p11);
        }
        rs0 += __shfl_xor_sync(0xffffffffu, rs0, 1);
        rs0 += __shfl_xor_sync(0xffffffffu, rs0, 2);
        rs1 += __shfl_xor_sync(0xffffffffu, rs1, 1);
        rs1 += __shfl_xor_sync(0xffffffffu, rs1, 2);
        l0 = l0 * sc0 + rs0; l1 = l1 * sc1 + rs1;
        m0 = M0; m1 = M1;
        #pragma unroll
        for (int ni = 0; ni < 16; ni++) {
            o_acc[ni][0] *= sc0; o_acc[ni][1] *= sc0;
            o_acc[ni][2] *= sc1; o_acc[ni][3] *= sc1;
        }

        // P: C-fragment layout -> A-fragment layout via quad shuffles
        uint32_t pa[8][4];
        const int src0 = (lane & ~3) | (tg >> 1);
        const int src1 = src0 + 2;
        const bool odd = (tg & 1) != 0;
        #pragma unroll
        for (int jc = 0; jc < 8; jc++) {
            uint32_t v00 = __shfl_sync(0xffffffffu, pf[jc][0], src0);
            uint32_t v01 = __shfl_sync(0xffffffffu, pf[jc][1], src0);
            uint32_t v02 = __shfl_sync(0xffffffffu, pf[jc][2], src0);
            uint32_t v03 = __shfl_sync(0xffffffffu, pf[jc][3], src0);
            uint32_t v10 = __shfl_sync(0xffffffffu, pf[jc][0], src1);
            uint32_t v11 = __shfl_sync(0xffffffffu, pf[jc][1], src1);
            uint32_t v12 = __shfl_sync(0xffffffffu, pf[jc][2], src1);
            uint32_t v13 = __shfl_sync(0xffffffffu, pf[jc][3], src1);
            pa[jc][0] = odd ? v01 : v00;
            pa[jc][1] = odd ? v03 : v02;
            pa[jc][2] = odd ? v11 : v10;
            pa[jc][3] = odd ? v13 : v12;
        }

        __syncthreads();
        // V tile -> smem (tf32), stride 136
        #pragma unroll
        for (int it = 0; it < 16; it++) {
            int idx = it * 128 + tid;
            int r = idx >> 5, c4 = (idx & 31) * 4;
            int kr = kt + r; if (kr >= S) kr = S - 1;
            float4 v = *reinterpret_cast<const float4*>(base + (size_t)kr * (3*D_MODEL) + 2 * D_MODEL + h * DH + c4);
            uint32_t* p = &KV[r * 136 + c4];
            p[0] = f2tf32(v.x); p[1] = f2tf32(v.y); p[2] = f2tf32(v.z); p[3] = f2tf32(v.w);
        }
        __syncthreads();

        // O += P V (16x128 per warp)
        #pragma unroll
        for (int jc = 0; jc < 8; jc++) {
            #pragma unroll
            for (int ni = 0; ni < 16; ni++) {
                uint32_t b0 = KV[(jc * 8 + tg) * 136 + ni * 8 + g];
                uint32_t b1 = KV[(jc * 8 + tg + 4) * 136 + ni * 8 + g];
                mma_tf32(o_acc[ni][0], o_acc[ni][1], o_acc[ni][2], o_acc[ni][3],
                         pa[jc][0], pa[jc][1], pa[jc][2], pa[jc][3], b0, b1);
            }
        }
    }

    const float inv0 = 1.f / l0, inv1 = 1.f / l1;
    const int r0 = q0 + wid * 16 + g, r1 = r0 + 8;
    #pragma unroll
    for (int ni = 0; ni < 16; ni++) {
        const int c = h * DH + ni * 8 + tg * 2;
        if (r0 < S)
            *reinterpret_cast<float2*>(out + (size_t)(b * S + r0) * D_MODEL + c) =
                make_float2(o_acc[ni][0] * inv0, o_acc[ni][1] * inv0);
        if (r1 < S)
            *reinterpret_cast<float2*>(out + (size_t)(b * S + r1) * D_MODEL + c) =
                make_float2(o_acc[ni][2] * inv1, o_acc[ni][3] * inv1);
    }
}

// ---------------- relay attention (16 tokens) ----------------
__global__ __launch_bounds__(128)
void relay_attn(long rqkv_off, long ratt_off)
{
    const float* __restrict__ rqkv = g_scratch + rqkv_off;
    float* __restrict__ rattn = g_scratch + ratt_off;

    const int h = blockIdx.x, b = blockIdx.y;
    __shared__ float q[16][128], k[16][128], v[16][128];
    __shared__ float p[16][16];
    const int tid = threadIdx.x;

    #pragma unroll
    for (int it = 0; it < 4; it++) {
        int idx4 = it * 128 + tid;
        int r = idx4 >> 5, c = (idx4 & 31) * 4;
        const float* rowp = rqkv + (size_t)(b * 16 + r) * (3 * D_MODEL);
        *reinterpret_cast<float4*>(&q[r][c]) = *reinterpret_cast<const float4*>(rowp + h * DH + c);
        *reinterpret_cast<float4*>(&k[r][c]) = *reinterpret_cast<const float4*>(rowp + D_MODEL + h * DH + c);
        *reinterpret_cast<float4*>(&v[r][c]) = *reinterpret_cast<const float4*>(rowp + 2 * D_MODEL + h * DH + c);
    }
    __syncthreads();

    #pragma unroll
    for (int t = 0; t < 2; t++) {
        int ij = tid * 2 + t;
        int i = ij >> 4, j = ij & 15;
        float s = 0.f;
        for (int d = 0; d < 128; d += 4) {
            float4 qa = *reinterpret_cast<float4*>(&q[i][d]);
            float4 ka = *reinterpret_cast<float4*>(&k[j][d]);
            s += qa.x*ka.x + qa.y*ka.y + qa.z*ka.z + qa.w*ka.w;
        }
        p[i][j] = s;
    }
    __syncthreads();

    if (tid < 16) {
        float mx = -1e30f;
        #pragma unroll
        for (int j = 0; j < 16; j++) mx = fmaxf(mx, p[tid][j]);
        float sum = 0.f; float e[16];
        #pragma unroll
        for (int j = 0; j < 16; j++) { e[j] = __expf(p[tid][j] - mx); sum += e[j]; }
        float inv = 1.0f / sum;
        #pragma unroll
        for (int j = 0; j < 16; j++) p[tid][j] = e[j] * inv;
    }
    __syncthreads();

    const int i = tid >> 3, c0 = (tid & 7) * 16;
    #pragma unroll
    for (int c = 0; c < 16; c++) {
        float o = 0.f;
        #pragma unroll
        for (int j = 0; j < 16; j++) o += p[i][j] * v[j][c0 + c];
        rattn[(size_t)(b * 16 + i) * D_MODEL + h * DH + c0 + c] = o;
    }
}

// ---------------- small glue kernels ----------------
__global__ void init_xs(const float* __restrict__ x, const float* __restrict__ relay_emb)
{
    float* __restrict__ xs = g_scratch + OFF_XS;
    const int row = blockIdx.x;
    const int b = row / SEQ, sr = row % SEQ;
    const int grp = sr / (GRP + 1), w = sr % (GRP + 1);
    float4 val;
    if (w == 0)
        val = reinterpret_cast<const float4*>(relay_emb)[threadIdx.x];
    else {
        int t = grp * GRP + (w - 1);
        val = reinterpret_cast<const float4*>(x + (size_t)(b * TOKENS + t) * D_MODEL)[threadIdx.x];
    }
    reinterpret_cast<float4*>(xs + (size_t)row * D_MODEL)[threadIdx.x] = val;
}

__global__ void relay_scatter(long rprj_off, const float* __restrict__ bias)
{
    const float* __restrict__ rproj = g_scratch + rprj_off;
    float* __restrict__ xs = g_scratch + OFF_XS;
    const int row = blockIdx.x;
    float4 r = reinterpret_cast<const float4*>(rproj + (size_t)row * D_MODEL)[threadIdx.x];
    float4 bb = reinterpret_cast<const float4*>(bias)[threadIdx.x];
    float4* dst = reinterpret_cast<float4*>(xs + (size_t)row * (GRP + 1) * D_MODEL) + threadIdx.x;
    float4 c = *dst;
    c.x += r.x + bb.x; c.y += r.y + bb.y; c.z += r.z + bb.z; c.w += r.w + bb.w;
    *dst = c;
}

__global__ void final_out(float* __restrict__ out)
{
    const float* __restrict__ xs = g_scratch + OFF_XS;
    const int row = blockIdx.x;
    const int b = row / TOKENS, t = row % TOKENS;
    const int src = b * SEQ + (t >> 7) * (GRP + 1) + 1 + (t & 127);
    reinterpret_cast<float4*>(out + (size_t)row * D_MODEL)[threadIdx.x] =
        reinterpret_cast<const float4*>(xs + (size_t)src * D_MODEL)[threadIdx.x];
}

// ---------------- host side ----------------
static void launch_gemm(int ep, long a_off, const float* B, const float* bias,
                        long c_off, int M, int N, int K)
{
    dim3 grid(N / 128, (M + 127) / 128);
    switch (ep) {
        case 0: gemm_tf32<0><<<grid, 256>>>(a_off, B, bias, c_off, M, N, K); break;
        case 3: gemm_tf32<3><<<grid, 256>>>(a_off, B, bias, c_off, M, N, K); break;
        case 5: gemm_tf32<5><<<grid, 256>>>(a_off, B, bias, c_off, M, N, K); break;
    }
}

extern "C" void kernel_launch(void* const* d_in, const int* in_sizes, int n_in,
                              void* d_out, int out_size)
{
    const float* x         = (const float*)d_in[0];
    const float* relay_emb = (const float*)d_in[1];
    const float* r_ln_g    = (const float*)d_in[2];
    const float* r_ln_b    = (const float*)d_in[3];
    const float* r_qkv     = (const float*)d_in[4];
    const float* r_ow      = (const float*)d_in[5];
    const float* r_ob      = (const float*)d_in[6];
    const float* l_ln_g    = (const float*)d_in[7];
    const float* l_ln_b    = (const float*)d_in[8];
    const float* l_qkv     = (const float*)d_in[9];
    const float* l_ow      = (const float*)d_in[10];
    const float* l_ob      = (const float*)d_in[11];
    const float* f_ln_g    = (const float*)d_in[12];
    const float* f_ln_b    = (const float*)d_in[13];
    const float* f_w1      = (const float*)d_in[14];
    const float* f_b1      = (const float*)d_in[15];
    const float* f_w2      = (const float*)d_in[16];
    const float* f_b2      = (const float*)d_in[17];

    init_xs<<<MROWS, 256>>>(x, relay_emb);

    for (int l = 0; l < DEPTH; l++) {
        const float* rqkv_w = r_qkv + (size_t)l * D_MODEL * 3 * D_MODEL;
        const float* row_w  = r_ow  + (size_t)l * D_MODEL * D_MODEL;
        const float* lqkv_w = l_qkv + (size_t)l * D_MODEL * 3 * D_MODEL;
        const float* low_w  = l_ow  + (size_t)l * D_MODEL * D_MODEL;
        const float* w1     = f_w1  + (size_t)l * D_MODEL * DFF;
        const float* w2     = f_w2  + (size_t)l * DFF * D_MODEL;

        // ---- relay attention over the 16 relay tokens per batch ----
        ln_kernel<<<32, 256>>>(OFF_XS, OFF_RLN, r_ln_g + l * D_MODEL, r_ln_b + l * D_MODEL,
                               (long)(GRP + 1) * D_MODEL, D_MODEL);
        launch_gemm(0, OFF_RLN, rqkv_w, nullptr, OFF_RQKV, 32, 3 * D_MODEL, D_MODEL);
        relay_attn<<<dim3(HEADS, BATCH), 128>>>(OFF_RQKV, OFF_RATT);
        launch_gemm(0, OFF_RATT, row_w, nullptr, OFF_RPRJ, 32, D_MODEL, D_MODEL);
        relay_scatter<<<32, 256>>>(OFF_RPRJ, r_ob + l * D_MODEL);

        // ---- full attention over stitched sequence ----
        ln_kernel<<<MROWS, 256>>>(OFF_XS, OFF_Y, l_ln_g + l * D_MODEL, l_ln_b + l * D_MODEL,
                                  D_MODEL, D_MODEL);
        launch_gemm(0, OFF_Y, lqkv_w, nullptr, OFF_QKV, MROWS, 3 * D_MODEL, D_MODEL);
        flash_attn_mma<<<dim3((SEQ + 63) / 64, HEADS, BATCH), 128>>>(OFF_QKV, OFF_ATT, SEQ);
        launch_gemm(3, OFF_ATT, low_w, l_ob + l * D_MODEL, OFF_XS, MROWS, D_MODEL, D_MODEL);

        // ---- FFN ----
        ln_kernel<<<MROWS, 256>>>(OFF_XS, OFF_Y, f_ln_g + l * D_MODEL, f_ln_b + l * D_MODEL,
                                  D_MODEL, D_MODEL);
        launch_gemm(5, OFF_Y, w1, f_b1 + l * DFF, OFF_FFN, MROWS, DFF, D_MODEL);
        launch_gemm(3, OFF_FFN, w2, f_b2 + l * D_MODEL, OFF_XS, MROWS, D_MODEL, DFF);
    }

    final_out<<<BATCH * TOKENS, 256>>>((float*)d_out);
}

// round 11
// speedup vs baseline: 4.7603x; 1.8010x over previous
#include <cuda_runtime.h>
#include <cuda_fp16.h>
#include <cstdint>
#include <math.h>

// ---------------- problem constants ----------------
#define D_MODEL 1024
#define HEADS   8
#define DH      128
#define DEPTH   2
#define BATCH   2
#define TOKENS  2048
#define GRP     128
#define NGRP    16
#define SEQ     2064
#define MROWS   (BATCH*SEQ)    // 4128
#define DFF     4096

// ---------------- scratch (floats) ----------------
#define OFF_XS    0L
#define SZ_XS     ((long)MROWS*D_MODEL)
#define OFF_Y     (OFF_XS + SZ_XS)
#define SZ_Y      ((long)MROWS*D_MODEL)
#define OFF_QKV   (OFF_Y + SZ_Y)
#define SZ_QKV    ((long)MROWS*3*D_MODEL)
#define OFF_ATT   (OFF_QKV + SZ_QKV)
#define SZ_ATT    ((long)MROWS*D_MODEL)
#define OFF_FFN   (OFF_ATT + SZ_ATT)
#define SZ_FFN    ((long)MROWS*DFF)
#define OFF_RLN   (OFF_FFN + SZ_FFN)
#define SZ_RLN    (32L*D_MODEL)
#define OFF_RQKV  (OFF_RLN + SZ_RLN)
#define SZ_RQKV   (32L*3*D_MODEL)
#define OFF_RATT  (OFF_RQKV + SZ_RQKV)
#define SZ_RATT   (32L*D_MODEL)
#define OFF_RPRJ  (OFF_RATT + SZ_RATT)
#define SZ_RPRJ   (32L*D_MODEL)
#define SCRATCH_FLOATS (OFF_RPRJ + SZ_RPRJ)

__device__ float g_scratch[SCRATCH_FLOATS];

// ---------------- helpers ----------------
__device__ __forceinline__ uint32_t smem_u32(const void* p) {
    uint32_t a;
    asm("{ .reg .u64 t; cvta.to.shared.u64 t, %1; cvt.u32.u64 %0, t; }" : "=r"(a) : "l"(p));
    return a;
}

__device__ __forceinline__ uint32_t pack_h2(float lo, float hi) {
    __half2 h = __floats2half2_rn(lo, hi);   // low 16 bits = lo
    return *reinterpret_cast<uint32_t*>(&h);
}

__device__ __forceinline__ void mma_f16(float& d0, float& d1, float& d2, float& d3,
                                        uint32_t a0, uint32_t a1, uint32_t a2, uint32_t a3,
                                        uint32_t b0, uint32_t b1)
{
    asm volatile("mma.sync.aligned.m16n8k16.row.col.f32.f16.f16.f32 "
                 "{%0,%1,%2,%3}, {%4,%5,%6,%7}, {%8,%9}, {%0,%1,%2,%3};\n"
                 : "+f"(d0), "+f"(d1), "+f"(d2), "+f"(d3)
                 : "r"(a0), "r"(a1), "r"(a2), "r"(a3), "r"(b0), "r"(b1));
}

__device__ __forceinline__ void ldsm_x4_trans(uint32_t& r0, uint32_t& r1,
                                              uint32_t& r2, uint32_t& r3, uint32_t addr)
{
    asm volatile("ldmatrix.sync.aligned.m8n8.x4.trans.shared.b16 {%0,%1,%2,%3}, [%4];"
                 : "=r"(r0), "=r"(r1), "=r"(r2), "=r"(r3) : "r"(addr));
}

// ================= fp16 mma GEMM =================
// C = A(MxK) @ B(KxN), row-major fp32 in/out, fp16 mma, fp32 accum.
// Block 128x128, BK=32, 8 warps (2x4), warp tile 64x32, m16n8k16.
// A smem: [128 m][20 half2-words] (16 data + 4 pad; stride 20 ≡ 20 mod 32 -> frag LDS conflict-free)
// B smem: row-major [32 k][68 half2-words]; fragments via ldmatrix.x4.trans
//         (row stride 272B; 272 mod 128 = 16 -> each LDSM phase hits 8 disjoint 16B spans)
// EP bits: 1=+bias, 2=residual-accumulate, 4=leaky_relu(0.01)
template<int EP>
__global__ __launch_bounds__(256)
void gemm_f16(long a_off, const float* __restrict__ B,
              const float* __restrict__ bias, long c_off,
              int M, int N, int K)
{
    __shared__ __align__(16) uint32_t As[2][128 * 20];
    __shared__ __align__(16) uint32_t Bs[2][32 * 68];

    const float* __restrict__ A = g_scratch + a_off;
    float* __restrict__ C = g_scratch + c_off;

    const int tid = threadIdx.x;
    const int lane = tid & 31;
    const int wid = tid >> 5;
    const int warp_m = wid >> 2;        // 0..1
    const int warp_n = wid & 3;         // 0..3
    const int g  = lane >> 2;
    const int tg = lane & 3;
    const int bm = blockIdx.y * 128;
    const int bn = blockIdx.x * 128;

    const uint32_t bsB = smem_u32(&Bs[0][0]);

    // staging: A 128x32 = 1024 float4, B 32x128 = 1024 float4; 4 float4 per thread each
    int a_r[4], a_c[4], a_gr[4], b_k[4], b_n[4];
    #pragma unroll
    for (int i = 0; i < 4; i++) {
        int idx = tid + i * 256;
        a_r[i] = idx >> 3;  a_c[i] = (idx & 7) * 4;
        b_k[i] = idx >> 5;  b_n[i] = (idx & 31) * 4;
        int r = bm + a_r[i];
        a_gr[i] = (r < M) ? r : (M - 1);
    }

    float acc[4][4][4];
    #pragma unroll
    for (int mi = 0; mi < 4; mi++)
        #pragma unroll
        for (int ni = 0; ni < 4; ni++)
            #pragma unroll
            for (int q = 0; q < 4; q++) acc[mi][ni][q] = 0.f;

    const int nk = K / 32;
    float4 aR[4], bR[4];

    // prologue: stage slab 0
    #pragma unroll
    for (int i = 0; i < 4; i++) {
        aR[i] = *reinterpret_cast<const float4*>(A + (size_t)a_gr[i] * K + a_c[i]);
        bR[i] = *reinterpret_cast<const float4*>(B + (size_t)b_k[i] * N + bn + b_n[i]);
    }
    #pragma unroll
    for (int i = 0; i < 4; i++) {
        uint2 ua = make_uint2(pack_h2(aR[i].x, aR[i].y), pack_h2(aR[i].z, aR[i].w));
        *reinterpret_cast<uint2*>(&As[0][a_r[i] * 20 + a_c[i] / 2]) = ua;
        uint2 ub = make_uint2(pack_h2(bR[i].x, bR[i].y), pack_h2(bR[i].z, bR[i].w));
        *reinterpret_cast<uint2*>(&Bs[0][b_k[i] * 68 + b_n[i] / 2]) = ub;
    }
    __syncthreads();

    for (int s = 0; s < nk; s++) {
        const int cur = s & 1;
        if (s + 1 < nk) {
            const int k0 = (s + 1) * 32;
            #pragma unroll
            for (int i = 0; i < 4; i++) {
                aR[i] = *reinterpret_cast<const float4*>(A + (size_t)a_gr[i] * K + k0 + a_c[i]);
                bR[i] = *reinterpret_cast<const float4*>(B + (size_t)(k0 + b_k[i]) * N + bn + b_n[i]);
            }
        }

        const uint32_t* __restrict__ as = As[cur];
        const uint32_t bbase = bsB + (uint32_t)cur * (32 * 68 * 4);
        #pragma unroll
        for (int ks = 0; ks < 2; ks++) {            // two k16 chunks per slab
            uint32_t bf[4][2];
            #pragma unroll
            for (int nip = 0; nip < 2; nip++) {     // two 16-col groups -> 4 n-octets
                const int krow = ks * 16 + (lane & 15);
                const int ncol = warp_n * 32 + nip * 16 + ((lane & 16) ? 8 : 0);
                const uint32_t addr = bbase + (uint32_t)(krow * 68 + (ncol >> 1)) * 4;
                ldsm_x4_trans(bf[nip*2][0], bf[nip*2][1], bf[nip*2+1][0], bf[nip*2+1][1], addr);
            }
            #pragma unroll
            for (int mi = 0; mi < 4; mi++) {
                const int r = warp_m * 64 + mi * 16 + g;
                uint32_t a0 = as[r * 20 + ks * 8 + tg];
                uint32_t a1 = as[(r + 8) * 20 + ks * 8 + tg];
                uint32_t a2 = as[r * 20 + ks * 8 + tg + 4];
                uint32_t a3 = as[(r + 8) * 20 + ks * 8 + tg + 4];
                #pragma unroll
                for (int ni = 0; ni < 4; ni++)
                    mma_f16(acc[mi][ni][0], acc[mi][ni][1], acc[mi][ni][2], acc[mi][ni][3],
                            a0, a1, a2, a3, bf[ni][0], bf[ni][1]);
            }
        }

        if (s + 1 < nk) {
            const int nxt = (s + 1) & 1;
            #pragma unroll
            for (int i = 0; i < 4; i++) {
                uint2 ua = make_uint2(pack_h2(aR[i].x, aR[i].y), pack_h2(aR[i].z, aR[i].w));
                *reinterpret_cast<uint2*>(&As[nxt][a_r[i] * 20 + a_c[i] / 2]) = ua;
                uint2 ub = make_uint2(pack_h2(bR[i].x, bR[i].y), pack_h2(bR[i].z, bR[i].w));
                *reinterpret_cast<uint2*>(&Bs[nxt][b_k[i] * 68 + b_n[i] / 2]) = ub;
            }
        }
        __syncthreads();
    }

    // epilogue (C-frag layout identical to validated tf32 version)
    #pragma unroll
    for (int mi = 0; mi < 4; mi++) {
        #pragma unroll
        for (int half = 0; half < 2; half++) {
            const int r = bm + warp_m * 64 + mi * 16 + g + half * 8;
            if (r >= M) continue;
            #pragma unroll
            for (int ni = 0; ni < 4; ni++) {
                float v0 = acc[mi][ni][half * 2 + 0];
                float v1 = acc[mi][ni][half * 2 + 1];
                const int c = bn + warp_n * 32 + ni * 8 + tg * 2;
                float* cp = C + (size_t)r * N + c;
                if (EP & 1) { v0 += bias[c]; v1 += bias[c + 1]; }
                if (EP & 4) {
                    v0 = v0 > 0.f ? v0 : 0.01f * v0;
                    v1 = v1 > 0.f ? v1 : 0.01f * v1;
                }
                if (EP & 2) {
                    float2 old = *reinterpret_cast<float2*>(cp);
                    v0 += old.x; v1 += old.y;
                }
                *reinterpret_cast<float2*>(cp) = make_float2(v0, v1);
            }
        }
    }
}

// ---------------- LayerNorm (row length 1024), strided ----------------
__global__ __launch_bounds__(256)
void ln_kernel(long in_off, long out_off,
               const float* __restrict__ gamma, const float* __restrict__ beta,
               long in_stride, long out_stride)
{
    const float* __restrict__ in = g_scratch + in_off;
    float* __restrict__ out = g_scratch + out_off;

    const int row = blockIdx.x;
    const int tid = threadIdx.x;
    const float4 v = reinterpret_cast<const float4*>(in + (size_t)row * in_stride)[tid];

    float s  = v.x + v.y + v.z + v.w;
    float sq = v.x*v.x + v.y*v.y + v.z*v.z + v.w*v.w;
    #pragma unroll
    for (int o = 16; o > 0; o >>= 1) {
        s  += __shfl_xor_sync(0xffffffffu, s,  o);
        sq += __shfl_xor_sync(0xffffffffu, sq, o);
    }
    __shared__ float ss[8], sqs[8];
    const int warp = tid >> 5;
    if ((tid & 31) == 0) { ss[warp] = s; sqs[warp] = sq; }
    __syncthreads();
    float ts = 0.f, tq = 0.f;
    #pragma unroll
    for (int w = 0; w < 8; w++) { ts += ss[w]; tq += sqs[w]; }
    const float mean = ts * (1.0f / D_MODEL);
    const float var  = tq * (1.0f / D_MODEL) - mean * mean;
    const float rstd = rsqrtf(var + 1e-5f);

    const float4 g4 = reinterpret_cast<const float4*>(gamma)[tid];
    const float4 b4 = reinterpret_cast<const float4*>(beta)[tid];
    float4 o;
    o.x = (v.x - mean) * rstd * g4.x + b4.x;
    o.y = (v.y - mean) * rstd * g4.y + b4.y;
    o.z = (v.z - mean) * rstd * g4.z + b4.z;
    o.w = (v.w - mean) * rstd * g4.w + b4.w;
    reinterpret_cast<float4*>(out + (size_t)row * out_stride)[tid] = o;
}

// ---------------- fp16 mma flash attention (unscaled dots!) ----------------
// Br=64 q rows/block, Bc=64 kv/tile, 4 warps; warp owns 16 full rows.
// Q/K/V share one smem buffer [64 rows][68 half2-words].
// S-phase: scalar-LDS B-frags from K (k = d, natural layout).
// PV-phase: P is already in A-frag layout (in-register pack), V via ldmatrix.x4.trans.
__global__ __launch_bounds__(128)
void flash_attn_f16(long qkv_off, long out_off, int S)
{
    __shared__ __align__(16) uint32_t KV[64 * 68];   // 17408 B

    const float* __restrict__ qkv = g_scratch + qkv_off;
    float* __restrict__ out = g_scratch + out_off;

    const int b = blockIdx.z, h = blockIdx.y;
    const int q0 = blockIdx.x * 64;
    const int tid = threadIdx.x;
    const int lane = tid & 31, wid = tid >> 5;
    const int g = lane >> 2, tg = lane & 3;
    const float* base = qkv + (size_t)b * S * (3 * D_MODEL);
    const uint32_t kvb = smem_u32(&KV[0]);

    // ---- stage Q (half2 along d), lift to A-frags ----
    #pragma unroll
    for (int it = 0; it < 16; it++) {
        int idx = it * 128 + tid;
        int r = idx >> 5, c4 = (idx & 31) * 4;
        int qr = q0 + r; if (qr >= S) qr = S - 1;
        float4 v = *reinterpret_cast<const float4*>(base + (size_t)qr * (3*D_MODEL) + h * DH + c4);
        *reinterpret_cast<uint2*>(&KV[r * 68 + c4 / 2]) =
            make_uint2(pack_h2(v.x, v.y), pack_h2(v.z, v.w));
    }
    __syncthreads();
    uint32_t qf[8][4];
    {
        const int qrow = wid * 16 + g;
        #pragma unroll
        for (int c = 0; c < 8; c++) {     // 8 k16 chunks over d=128
            qf[c][0] = KV[qrow * 68 + c * 8 + tg];
            qf[c][1] = KV[(qrow + 8) * 68 + c * 8 + tg];
            qf[c][2] = KV[qrow * 68 + c * 8 + tg + 4];
            qf[c][3] = KV[(qrow + 8) * 68 + c * 8 + tg + 4];
        }
    }

    float o_acc[16][4];
    #pragma unroll
    for (int ni = 0; ni < 16; ni++)
        o_acc[ni][0] = o_acc[ni][1] = o_acc[ni][2] = o_acc[ni][3] = 0.f;
    float m0 = -1e30f, m1 = -1e30f, l0 = 0.f, l1 = 0.f;

    for (int kt = 0; kt < S; kt += 64) {
        __syncthreads();   // Q-lift / prior PV reads complete
        // stage K [key][d half2]
        #pragma unroll
        for (int it = 0; it < 16; it++) {
            int idx = it * 128 + tid;
            int r = idx >> 5, c4 = (idx & 31) * 4;
            int kr = kt + r; if (kr >= S) kr = S - 1;
            float4 v = *reinterpret_cast<const float4*>(base + (size_t)kr * (3*D_MODEL) + D_MODEL + h * DH + c4);
            *reinterpret_cast<uint2*>(&KV[r * 68 + c4 / 2]) =
                make_uint2(pack_h2(v.x, v.y), pack_h2(v.z, v.w));
        }
        __syncthreads();

        // S = Q K^T : 8 d-chunks x 8 key-octets (16x64 per warp)
        float sf[8][4];
        #pragma unroll
        for (int ni = 0; ni < 8; ni++)
            sf[ni][0] = sf[ni][1] = sf[ni][2] = sf[ni][3] = 0.f;
        #pragma unroll
        for (int c = 0; c < 8; c++) {
            #pragma unroll
            for (int ni = 0; ni < 8; ni++) {
                uint32_t b0 = KV[(ni * 8 + g) * 68 + c * 8 + tg];
                uint32_t b1 = KV[(ni * 8 + g) * 68 + c * 8 + tg + 4];
                mma_f16(sf[ni][0], sf[ni][1], sf[ni][2], sf[ni][3],
                        qf[c][0], qf[c][1], qf[c][2], qf[c][3], b0, b1);
            }
        }

        // online softmax (rows g, g+8; quad shuffles finish each row)
        float mx0 = -1e30f, mx1 = -1e30f;
        #pragma unroll
        for (int ni = 0; ni < 8; ni++) {
            int c = kt + ni * 8 + tg * 2;
            if (c >= S)     { sf[ni][0] = -1e30f; sf[ni][2] = -1e30f; }
            if (c + 1 >= S) { sf[ni][1] = -1e30f; sf[ni][3] = -1e30f; }
            mx0 = fmaxf(mx0, fmaxf(sf[ni][0], sf[ni][1]));
            mx1 = fmaxf(mx1, fmaxf(sf[ni][2], sf[ni][3]));
        }
        mx0 = fmaxf(mx0, __shfl_xor_sync(0xffffffffu, mx0, 1));
        mx0 = fmaxf(mx0, __shfl_xor_sync(0xffffffffu, mx0, 2));
        mx1 = fmaxf(mx1, __shfl_xor_sync(0xffffffffu, mx1, 1));
        mx1 = fmaxf(mx1, __shfl_xor_sync(0xffffffffu, mx1, 2));
        const float M0 = fmaxf(m0, mx0), M1 = fmaxf(m1, mx1);
        const float sc0 = __expf(m0 - M0), sc1 = __expf(m1 - M1);
        float rs0 = 0.f, rs1 = 0.f;
        uint32_t ph[8][2];
        #pragma unroll
        for (int ni = 0; ni < 8; ni++) {
            float p00 = __expf(sf[ni][0] - M0);
            float p01 = __expf(sf[ni][1] - M0);
            float p10 = __expf(sf[ni][2] - M1);
            float p11 = __expf(sf[ni][3] - M1);
            rs0 += p00 + p01; rs1 += p10 + p11;
            ph[ni][0] = pack_h2(p00, p01);   // row g,  key octet ni
            ph[ni][1] = pack_h2(p10, p11);   // row g+8
        }
        rs0 += __shfl_xor_sync(0xffffffffu, rs0, 1);
        rs0 += __shfl_xor_sync(0xffffffffu, rs0, 2);
        rs1 += __shfl_xor_sync(0xffffffffu, rs1, 1);
        rs1 += __shfl_xor_sync(0xffffffffu, rs1, 2);
        l0 = l0 * sc0 + rs0; l1 = l1 * sc1 + rs1;
        m0 = M0; m1 = M1;
        #pragma unroll
        for (int ni = 0; ni < 16; ni++) {
            o_acc[ni][0] *= sc0; o_acc[ni][1] *= sc0;
            o_acc[ni][2] *= sc1; o_acc[ni][3] *= sc1;
        }

        __syncthreads();   // S-phase reads of K done
        // stage V [key][d half2]
        #pragma unroll
        for (int it = 0; it < 16; it++) {
            int idx = it * 128 + tid;
            int r = idx >> 5, c4 = (idx & 31) * 4;
            int kr = kt + r; if (kr >= S) kr = S - 1;
            float4 v = *reinterpret_cast<const float4*>(base + (size_t)kr * (3*D_MODEL) + 2 * D_MODEL + h * DH + c4);
            *reinterpret_cast<uint2*>(&KV[r * 68 + c4 / 2]) =
                make_uint2(pack_h2(v.x, v.y), pack_h2(v.z, v.w));
        }
        __syncthreads();

        // O += P V : A = P in-register (chunk jc = key-octets 2jc, 2jc+1)
        #pragma unroll
        for (int jc = 0; jc < 4; jc++) {
            uint32_t pa0 = ph[2*jc][0], pa1 = ph[2*jc][1];
            uint32_t pa2 = ph[2*jc+1][0], pa3 = ph[2*jc+1][1];
            #pragma unroll
            for (int nip = 0; nip < 8; nip++) {
                const int krow = jc * 16 + (lane & 15);
                const int dcol = nip * 16 + ((lane & 16) ? 8 : 0);
                const uint32_t addr = kvb + (uint32_t)(krow * 68 + (dcol >> 1)) * 4;
                uint32_t b00, b01, b10, b11;
                ldsm_x4_trans(b00, b01, b10, b11, addr);
                mma_f16(o_acc[nip*2][0], o_acc[nip*2][1], o_acc[nip*2][2], o_acc[nip*2][3],
                        pa0, pa1, pa2, pa3, b00, b01);
                mma_f16(o_acc[nip*2+1][0], o_acc[nip*2+1][1], o_acc[nip*2+1][2], o_acc[nip*2+1][3],
                        pa0, pa1, pa2, pa3, b10, b11);
            }
        }
    }

    const float inv0 = 1.f / l0, inv1 = 1.f / l1;
    const int r0 = q0 + wid * 16 + g, r1 = r0 + 8;
    #pragma unroll
    for (int ni = 0; ni < 16; ni++) {
        const int c = h * DH + ni * 8 + tg * 2;
        if (r0 < S)
            *reinterpret_cast<float2*>(out + (size_t)(b * S + r0) * D_MODEL + c) =
                make_float2(o_acc[ni][0] * inv0, o_acc[ni][1] * inv0);
        if (r1 < S)
            *reinterpret_cast<float2*>(out + (size_t)(b * S + r1) * D_MODEL + c) =
                make_float2(o_acc[ni][2] * inv1, o_acc[ni][3] * inv1);
    }
}

// ---------------- relay attention (16 tokens) ----------------
__global__ __launch_bounds__(128)
void relay_attn(long rqkv_off, long ratt_off)
{
    const float* __restrict__ rqkv = g_scratch + rqkv_off;
    float* __restrict__ rattn = g_scratch + ratt_off;

    const int h = blockIdx.x, b = blockIdx.y;
    __shared__ float q[16][128], k[16][128], v[16][128];
    __shared__ float p[16][16];
    const int tid = threadIdx.x;

    #pragma unroll
    for (int it = 0; it < 4; it++) {
        int idx4 = it * 128 + tid;
        int r = idx4 >> 5, c = (idx4 & 31) * 4;
        const float* rowp = rqkv + (size_t)(b * 16 + r) * (3 * D_MODEL);
        *reinterpret_cast<float4*>(&q[r][c]) = *reinterpret_cast<const float4*>(rowp + h * DH + c);
        *reinterpret_cast<float4*>(&k[r][c]) = *reinterpret_cast<const float4*>(rowp + D_MODEL + h * DH + c);
        *reinterpret_cast<float4*>(&v[r][c]) = *reinterpret_cast<const float4*>(rowp + 2 * D_MODEL + h * DH + c);
    }
    __syncthreads();

    #pragma unroll
    for (int t = 0; t < 2; t++) {
        int ij = tid * 2 + t;
        int i = ij >> 4, j = ij & 15;
        float s = 0.f;
        for (int d = 0; d < 128; d += 4) {
            float4 qa = *reinterpret_cast<float4*>(&q[i][d]);
            float4 ka = *reinterpret_cast<float4*>(&k[j][d]);
            s += qa.x*ka.x + qa.y*ka.y + qa.z*ka.z + qa.w*ka.w;
        }
        p[i][j] = s;
    }
    __syncthreads();

    if (tid < 16) {
        float mx = -1e30f;
        #pragma unroll
        for (int j = 0; j < 16; j++) mx = fmaxf(mx, p[tid][j]);
        float sum = 0.f; float e[16];
        #pragma unroll
        for (int j = 0; j < 16; j++) { e[j] = __expf(p[tid][j] - mx); sum += e[j]; }
        float inv = 1.0f / sum;
        #pragma unroll
        for (int j = 0; j < 16; j++) p[tid][j] = e[j] * inv;
    }
    __syncthreads();

    const int i = tid >> 3, c0 = (tid & 7) * 16;
    #pragma unroll
    for (int c = 0; c < 16; c++) {
        float o = 0.f;
        #pragma unroll
        for (int j = 0; j < 16; j++) o += p[i][j] * v[j][c0 + c];
        rattn[(size_t)(b * 16 + i) * D_MODEL + h * DH + c0 + c] = o;
    }
}

// ---------------- small glue kernels ----------------
__global__ void init_xs(const float* __restrict__ x, const float* __restrict__ relay_emb)
{
    float* __restrict__ xs = g_scratch + OFF_XS;
    const int row = blockIdx.x;
    const int b = row / SEQ, sr = row % SEQ;
    const int grp = sr / (GRP + 1), w = sr % (GRP + 1);
    float4 val;
    if (w == 0)
        val = reinterpret_cast<const float4*>(relay_emb)[threadIdx.x];
    else {
        int t = grp * GRP + (w - 1);
        val = reinterpret_cast<const float4*>(x + (size_t)(b * TOKENS + t) * D_MODEL)[threadIdx.x];
    }
    reinterpret_cast<float4*>(xs + (size_t)row * D_MODEL)[threadIdx.x] = val;
}

__global__ void relay_scatter(long rprj_off, const float* __restrict__ bias)
{
    const float* __restrict__ rproj = g_scratch + rprj_off;
    float* __restrict__ xs = g_scratch + OFF_XS;
    const int row = blockIdx.x;
    float4 r = reinterpret_cast<const float4*>(rproj + (size_t)row * D_MODEL)[threadIdx.x];
    float4 bb = reinterpret_cast<const float4*>(bias)[threadIdx.x];
    float4* dst = reinterpret_cast<float4*>(xs + (size_t)row * (GRP + 1) * D_MODEL) + threadIdx.x;
    float4 c = *dst;
    c.x += r.x + bb.x; c.y += r.y + bb.y; c.z += r.z + bb.z; c.w += r.w + bb.w;
    *dst = c;
}

__global__ void final_out(float* __restrict__ out)
{
    const float* __restrict__ xs = g_scratch + OFF_XS;
    const int row = blockIdx.x;
    const int b = row / TOKENS, t = row % TOKENS;
    const int src = b * SEQ + (t >> 7) * (GRP + 1) + 1 + (t & 127);
    reinterpret_cast<float4*>(out + (size_t)row * D_MODEL)[threadIdx.x] =
        reinterpret_cast<const float4*>(xs + (size_t)src * D_MODEL)[threadIdx.x];
}

// ---------------- host side ----------------
static void launch_gemm(int ep, long a_off, const float* B, const float* bias,
                        long c_off, int M, int N, int K)
{
    dim3 grid(N / 128, (M + 127) / 128);
    switch (ep) {
        case 0: gemm_f16<0><<<grid, 256>>>(a_off, B, bias, c_off, M, N, K); break;
        case 3: gemm_f16<3><<<grid, 256>>>(a_off, B, bias, c_off, M, N, K); break;
        case 5: gemm_f16<5><<<grid, 256>>>(a_off, B, bias, c_off, M, N, K); break;
    }
}

extern "C" void kernel_launch(void* const* d_in, const int* in_sizes, int n_in,
                              void* d_out, int out_size)
{
    const float* x         = (const float*)d_in[0];
    const float* relay_emb = (const float*)d_in[1];
    const float* r_ln_g    = (const float*)d_in[2];
    const float* r_ln_b    = (const float*)d_in[3];
    const float* r_qkv     = (const float*)d_in[4];
    const float* r_ow      = (const float*)d_in[5];
    const float* r_ob      = (const float*)d_in[6];
    const float* l_ln_g    = (const float*)d_in[7];
    const float* l_ln_b    = (const float*)d_in[8];
    const float* l_qkv     = (const float*)d_in[9];
    const float* l_ow      = (const float*)d_in[10];
    const float* l_ob      = (const float*)d_in[11];
    const float* f_ln_g    = (const float*)d_in[12];
    const float* f_ln_b    = (const float*)d_in[13];
    const float* f_w1      = (const float*)d_in[14];
    const float* f_b1      = (const float*)d_in[15];
    const float* f_w2      = (const float*)d_in[16];
    const float* f_b2      = (const float*)d_in[17];

    init_xs<<<MROWS, 256>>>(x, relay_emb);

    for (int l = 0; l < DEPTH; l++) {
        const float* rqkv_w = r_qkv + (size_t)l * D_MODEL * 3 * D_MODEL;
        const float* row_w  = r_ow  + (size_t)l * D_MODEL * D_MODEL;
        const float* lqkv_w = l_qkv + (size_t)l * D_MODEL * 3 * D_MODEL;
        const float* low_w  = l_ow  + (size_t)l * D_MODEL * D_MODEL;
        const float* w1     = f_w1  + (size_t)l * D_MODEL * DFF;
        const float* w2     = f_w2  + (size_t)l * DFF * D_MODEL;

        // ---- relay attention over the 16 relay tokens per batch ----
        ln_kernel<<<32, 256>>>(OFF_XS, OFF_RLN, r_ln_g + l * D_MODEL, r_ln_b + l * D_MODEL,
                               (long)(GRP + 1) * D_MODEL, D_MODEL);
        launch_gemm(0, OFF_RLN, rqkv_w, nullptr, OFF_RQKV, 32, 3 * D_MODEL, D_MODEL);
        relay_attn<<<dim3(HEADS, BATCH), 128>>>(OFF_RQKV, OFF_RATT);
        launch_gemm(0, OFF_RATT, row_w, nullptr, OFF_RPRJ, 32, D_MODEL, D_MODEL);
        relay_scatter<<<32, 256>>>(OFF_RPRJ, r_ob + l * D_MODEL);

        // ---- full attention over stitched sequence ----
        ln_kernel<<<MROWS, 256>>>(OFF_XS, OFF_Y, l_ln_g + l * D_MODEL, l_ln_b + l * D_MODEL,
                                  D_MODEL, D_MODEL);
        launch_gemm(0, OFF_Y, lqkv_w, nullptr, OFF_QKV, MROWS, 3 * D_MODEL, D_MODEL);
        flash_attn_f16<<<dim3((SEQ + 63) / 64, HEADS, BATCH), 128>>>(OFF_QKV, OFF_ATT, SEQ);
        launch_gemm(3, OFF_ATT, low_w, l_ob + l * D_MODEL, OFF_XS, MROWS, D_MODEL, D_MODEL);

        // ---- FFN ----
        ln_kernel<<<MROWS, 256>>>(OFF_XS, OFF_Y, f_ln_g + l * D_MODEL, f_ln_b + l * D_MODEL,
                                  D_MODEL, D_MODEL);
        launch_gemm(5, OFF_Y, w1, f_b1 + l * DFF, OFF_FFN, MROWS, DFF, D_MODEL);
        launch_gemm(3, OFF_FFN, w2, f_b2 + l * D_MODEL, OFF_XS, MROWS, D_MODEL, DFF);
    }

    final_out<<<BATCH * TOKENS, 256>>>((float*)d_out);
}

// round 13
// speedup vs baseline: 6.0880x; 1.2789x over previous
#include <cuda_runtime.h>
#include <cuda_fp16.h>
#include <cstdint>
#include <math.h>

// ---------------- problem constants ----------------
#define D_MODEL 1024
#define HEADS   8
#define DH      128
#define DEPTH   2
#define BATCH   2
#define TOKENS  2048
#define GRP     128
#define NGRP    16
#define SEQ     2064
#define MROWS   (BATCH*SEQ)    // 4128
#define DFF     4096

// ---------------- fp32 scratch ----------------
#define OFF_XS    0L
#define SZ_XS     ((long)MROWS*D_MODEL)
#define OFF_RPRJ  (OFF_XS + SZ_XS)
#define SZ_RPRJ   (32L*D_MODEL)
#define SCRATCH_FLOATS (OFF_RPRJ + SZ_RPRJ)

__device__ float g_scratch[SCRATCH_FLOATS];

// ---------------- fp16 scratch (offsets in halves) ----------------
// per-layer weight block: rqkv 3145728 | row 1048576 | lqkv 3145728 | low 1048576 | fw1 4194304 | fw2 4194304
#define WBLK      16777216L
#define W_RQKV    0L
#define W_ROW     3145728L
#define W_LQKV    4194304L
#define W_LOW     7340032L
#define W_FW1     8388608L
#define W_FW2     12582912L
#define HOFF_W    0L
#define SZ_W      (2*WBLK)
#define HOFF_Y    (HOFF_W + SZ_W)
#define SZ_HY     ((long)MROWS*D_MODEL)
#define HOFF_QKV  (HOFF_Y + SZ_HY)
#define SZ_HQKV   ((long)MROWS*3*D_MODEL)
#define HOFF_ATT  (HOFF_QKV + SZ_HQKV)
#define SZ_HATT   ((long)MROWS*D_MODEL)
#define HOFF_FFN  (HOFF_ATT + SZ_HATT)
#define SZ_HFFN   ((long)MROWS*DFF)
#define HOFF_RLN  (HOFF_FFN + SZ_HFFN)
#define SZ_HRLN   (32L*D_MODEL)
#define HOFF_RQKV (HOFF_RLN + SZ_HRLN)
#define SZ_HRQKV  (32L*3*D_MODEL)
#define HOFF_RATT (HOFF_RQKV + SZ_HRQKV)
#define SZ_HRATT  (32L*D_MODEL)
#define HSCRATCH_HALVES (HOFF_RATT + SZ_HRATT)

__device__ __align__(16) __half g_hscratch[HSCRATCH_HALVES];

// ---------------- helpers ----------------
__device__ __forceinline__ uint32_t smem_u32(const void* p) {
    uint32_t a;
    asm("{ .reg .u64 t; cvta.to.shared.u64 t, %1; cvt.u32.u64 %0, t; }" : "=r"(a) : "l"(p));
    return a;
}

__device__ __forceinline__ uint32_t pack_h2(float lo, float hi) {
    __half2 h = __floats2half2_rn(lo, hi);   // low 16 bits = lo
    return *reinterpret_cast<uint32_t*>(&h);
}

__device__ __forceinline__ void mma_f16(float& d0, float& d1, float& d2, float& d3,
                                        uint32_t a0, uint32_t a1, uint32_t a2, uint32_t a3,
                                        uint32_t b0, uint32_t b1)
{
    asm volatile("mma.sync.aligned.m16n8k16.row.col.f32.f16.f16.f32 "
                 "{%0,%1,%2,%3}, {%4,%5,%6,%7}, {%8,%9}, {%0,%1,%2,%3};\n"
                 : "+f"(d0), "+f"(d1), "+f"(d2), "+f"(d3)
                 : "r"(a0), "r"(a1), "r"(a2), "r"(a3), "r"(b0), "r"(b1));
}

__device__ __forceinline__ void ldsm_x4_trans(uint32_t& r0, uint32_t& r1,
                                              uint32_t& r2, uint32_t& r3, uint32_t addr)
{
    asm volatile("ldmatrix.sync.aligned.m8n8.x4.trans.shared.b16 {%0,%1,%2,%3}, [%4];"
                 : "=r"(r0), "=r"(r1), "=r"(r2), "=r"(r3) : "r"(addr));
}

// ---------------- fp32 -> fp16 weight conversion ----------------
// n must be a multiple of 2048; each thread converts 8 elems.
__global__ __launch_bounds__(256)
void cvt_h(const float* __restrict__ src, long dst_off, long n)
{
    __half* __restrict__ dst = g_hscratch + dst_off;
    long i = ((long)blockIdx.x * 256 + threadIdx.x) * 8;
    float4 a = *reinterpret_cast<const float4*>(src + i);
    float4 b = *reinterpret_cast<const float4*>(src + i + 4);
    uint4 u = make_uint4(pack_h2(a.x, a.y), pack_h2(a.z, a.w),
                         pack_h2(b.x, b.y), pack_h2(b.z, b.w));
    *reinterpret_cast<uint4*>(dst + i) = u;
}

// ================= fp16-in fp16/fp32-out mma GEMM =================
// C = A(MxK) @ B(KxN); A,B fp16 (g_hscratch offsets), C fp32 (g_scratch) or fp16 (bit 8).
// EP bits: 1=+bias(f32), 2=residual-accumulate(f32 C), 4=leaky_relu, 8=fp16 output
// Block 128x128, BK=32, 8 warps (2x4), warp tile 64x32, m16n8k16.
template<int EP>
__global__ __launch_bounds__(256)
void gemm_h16(long a_off, long b_off, const float* __restrict__ bias, long c_off,
              int M, int N, int K)
{
    __shared__ __align__(16) uint32_t As[2][128 * 20];   // [m][16 data + 4 pad] half2 words
    __shared__ __align__(16) uint32_t Bs[2][32 * 68];    // [k][64 data + 4 pad] half2 words

    const __half* __restrict__ A = g_hscratch + a_off;
    const __half* __restrict__ B = g_hscratch + b_off;

    const int tid = threadIdx.x;
    const int lane = tid & 31;
    const int wid = tid >> 5;
    const int warp_m = wid >> 2;
    const int warp_n = wid & 3;
    const int g  = lane >> 2;
    const int tg = lane & 3;
    const int bm = blockIdx.y * 128;
    const int bn = blockIdx.x * 128;

    const uint32_t bsB = smem_u32(&Bs[0][0]);

    // staging: A tile 128x32 halves = 512 uint4; B tile 32x128 halves = 512 uint4; 2 each
    int a_r[2], a_q[2], a_gr[2], b_r[2], b_q[2];
    #pragma unroll
    for (int i = 0; i < 2; i++) {
        int idx = tid + i * 256;
        a_r[i] = idx >> 2;  a_q[i] = idx & 3;
        b_r[i] = idx >> 4;  b_q[i] = idx & 15;
        int r = bm + a_r[i];
        a_gr[i] = (r < M) ? r : (M - 1);
    }

    float acc[4][4][4];
    #pragma unroll
    for (int mi = 0; mi < 4; mi++)
        #pragma unroll
        for (int ni = 0; ni < 4; ni++)
            #pragma unroll
            for (int q = 0; q < 4; q++) acc[mi][ni][q] = 0.f;

    const int nk = K / 32;
    uint4 aR[2], bR[2];

    #pragma unroll
    for (int i = 0; i < 2; i++) {
        aR[i] = *reinterpret_cast<const uint4*>(A + (size_t)a_gr[i] * K + a_q[i] * 8);
        bR[i] = *reinterpret_cast<const uint4*>(B + (size_t)b_r[i] * N + bn + b_q[i] * 8);
    }
    #pragma unroll
    for (int i = 0; i < 2; i++) {
        *reinterpret_cast<uint4*>(&As[0][a_r[i] * 20 + a_q[i] * 4]) = aR[i];
        *reinterpret_cast<uint4*>(&Bs[0][b_r[i] * 68 + b_q[i] * 4]) = bR[i];
    }
    __syncthreads();

    for (int s = 0; s < nk; s++) {
        const int cur = s & 1;
        if (s + 1 < nk) {
            const int k0 = (s + 1) * 32;
            #pragma unroll
            for (int i = 0; i < 2; i++) {
                aR[i] = *reinterpret_cast<const uint4*>(A + (size_t)a_gr[i] * K + k0 + a_q[i] * 8);
                bR[i] = *reinterpret_cast<const uint4*>(B + (size_t)(k0 + b_r[i]) * N + bn + b_q[i] * 8);
            }
        }

        const uint32_t* __restrict__ as = As[cur];
        const uint32_t bbase = bsB + (uint32_t)cur * (32 * 68 * 4);
        #pragma unroll
        for (int ks = 0; ks < 2; ks++) {
            uint32_t bf[4][2];
            #pragma unroll
            for (int nip = 0; nip < 2; nip++) {
                const int krow = ks * 16 + (lane & 15);
                const int ncol = warp_n * 32 + nip * 16 + ((lane & 16) ? 8 : 0);
                const uint32_t addr = bbase + (uint32_t)(krow * 68 + (ncol >> 1)) * 4;
                ldsm_x4_trans(bf[nip*2][0], bf[nip*2][1], bf[nip*2+1][0], bf[nip*2+1][1], addr);
            }
            #pragma unroll
            for (int mi = 0; mi < 4; mi++) {
                const int r = warp_m * 64 + mi * 16 + g;
                uint32_t a0 = as[r * 20 + ks * 8 + tg];
                uint32_t a1 = as[(r + 8) * 20 + ks * 8 + tg];
                uint32_t a2 = as[r * 20 + ks * 8 + tg + 4];
                uint32_t a3 = as[(r + 8) * 20 + ks * 8 + tg + 4];
                #pragma unroll
                for (int ni = 0; ni < 4; ni++)
                    mma_f16(acc[mi][ni][0], acc[mi][ni][1], acc[mi][ni][2], acc[mi][ni][3],
                            a0, a1, a2, a3, bf[ni][0], bf[ni][1]);
            }
        }

        if (s + 1 < nk) {
            const int nxt = (s + 1) & 1;
            #pragma unroll
            for (int i = 0; i < 2; i++) {
                *reinterpret_cast<uint4*>(&As[nxt][a_r[i] * 20 + a_q[i] * 4]) = aR[i];
                *reinterpret_cast<uint4*>(&Bs[nxt][b_r[i] * 68 + b_q[i] * 4]) = bR[i];
            }
        }
        __syncthreads();
    }

    // epilogue
    #pragma unroll
    for (int mi = 0; mi < 4; mi++) {
        #pragma unroll
        for (int half = 0; half < 2; half++) {
            const int r = bm + warp_m * 64 + mi * 16 + g + half * 8;
            if (r >= M) continue;
            #pragma unroll
            for (int ni = 0; ni < 4; ni++) {
                float v0 = acc[mi][ni][half * 2 + 0];
                float v1 = acc[mi][ni][half * 2 + 1];
                const int c = bn + warp_n * 32 + ni * 8 + tg * 2;
                if (EP & 1) { v0 += bias[c]; v1 += bias[c + 1]; }
                if (EP & 4) {
                    v0 = v0 > 0.f ? v0 : 0.01f * v0;
                    v1 = v1 > 0.f ? v1 : 0.01f * v1;
                }
                if (EP & 8) {
                    __half* cp = g_hscratch + c_off + (size_t)r * N + c;
                    *reinterpret_cast<uint32_t*>(cp) = pack_h2(v0, v1);
                } else {
                    float* cp = g_scratch + c_off + (size_t)r * N + c;
                    if (EP & 2) {
                        float2 old = *reinterpret_cast<float2*>(cp);
                        v0 += old.x; v1 += old.y;
                    }
                    *reinterpret_cast<float2*>(cp) = make_float2(v0, v1);
                }
            }
        }
    }
}

// ---------------- LayerNorm: fp32 in (strided), fp16 out [row][1024] ----------------
__global__ __launch_bounds__(256)
void ln_kernel(long in_off, long out_off_h,
               const float* __restrict__ gamma, const float* __restrict__ beta,
               long in_stride)
{
    const float* __restrict__ in = g_scratch + in_off;
    __half* __restrict__ out = g_hscratch + out_off_h;

    const int row = blockIdx.x;
    const int tid = threadIdx.x;
    const float4 v = reinterpret_cast<const float4*>(in + (size_t)row * in_stride)[tid];

    float s  = v.x + v.y + v.z + v.w;
    float sq = v.x*v.x + v.y*v.y + v.z*v.z + v.w*v.w;
    #pragma unroll
    for (int o = 16; o > 0; o >>= 1) {
        s  += __shfl_xor_sync(0xffffffffu, s,  o);
        sq += __shfl_xor_sync(0xffffffffu, sq, o);
    }
    __shared__ float ss[8], sqs[8];
    const int warp = tid >> 5;
    if ((tid & 31) == 0) { ss[warp] = s; sqs[warp] = sq; }
    __syncthreads();
    float ts = 0.f, tq = 0.f;
    #pragma unroll
    for (int w = 0; w < 8; w++) { ts += ss[w]; tq += sqs[w]; }
    const float mean = ts * (1.0f / D_MODEL);
    const float var  = tq * (1.0f / D_MODEL) - mean * mean;
    const float rstd = rsqrtf(var + 1e-5f);

    const float4 g4 = reinterpret_cast<const float4*>(gamma)[tid];
    const float4 b4 = reinterpret_cast<const float4*>(beta)[tid];
    float o0 = (v.x - mean) * rstd * g4.x + b4.x;
    float o1 = (v.y - mean) * rstd * g4.y + b4.y;
    float o2 = (v.z - mean) * rstd * g4.z + b4.z;
    float o3 = (v.w - mean) * rstd * g4.w + b4.w;
    *reinterpret_cast<uint2*>(out + (size_t)row * D_MODEL + tid * 4) =
        make_uint2(pack_h2(o0, o1), pack_h2(o2, o3));
}

// ---------------- fp16 flash attention (unscaled dots!), fp16 in/out ----------------
__global__ __launch_bounds__(128)
void flash_attn_f16(long qkv_off, long out_off, int S)
{
    __shared__ __align__(16) uint32_t KV[64 * 68];   // 17408 B

    const __half* __restrict__ qkv = g_hscratch + qkv_off;
    __half* __restrict__ out = g_hscratch + out_off;

    const int b = blockIdx.z, h = blockIdx.y;
    const int q0 = blockIdx.x * 64;
    const int tid = threadIdx.x;
    const int lane = tid & 31, wid = tid >> 5;
    const int g = lane >> 2, tg = lane & 3;
    const __half* base = qkv + (size_t)b * S * (3 * D_MODEL);
    const uint32_t kvb = smem_u32(&KV[0]);

    // ---- stage Q (uint4 = 8 halves), lift to A-frags ----
    #pragma unroll
    for (int it = 0; it < 8; it++) {
        int idx = it * 128 + tid;
        int r = idx >> 4, q = idx & 15;
        int qr = q0 + r; if (qr >= S) qr = S - 1;
        uint4 v = *reinterpret_cast<const uint4*>(base + (size_t)qr * (3*D_MODEL) + h * DH + q * 8);
        *reinterpret_cast<uint4*>(&KV[r * 68 + q * 4]) = v;
    }
    __syncthreads();
    uint32_t qf[8][4];
    {
        const int qrow = wid * 16 + g;
        #pragma unroll
        for (int c = 0; c < 8; c++) {
            qf[c][0] = KV[qrow * 68 + c * 8 + tg];
            qf[c][1] = KV[(qrow + 8) * 68 + c * 8 + tg];
            qf[c][2] = KV[qrow * 68 + c * 8 + tg + 4];
            qf[c][3] = KV[(qrow + 8) * 68 + c * 8 + tg + 4];
        }
    }

    float o_acc[16][4];
    #pragma unroll
    for (int ni = 0; ni < 16; ni++)
        o_acc[ni][0] = o_acc[ni][1] = o_acc[ni][2] = o_acc[ni][3] = 0.f;
    float m0 = -1e30f, m1 = -1e30f, l0 = 0.f, l1 = 0.f;

    for (int kt = 0; kt < S; kt += 64) {
        __syncthreads();
        // stage K
        #pragma unroll
        for (int it = 0; it < 8; it++) {
            int idx = it * 128 + tid;
            int r = idx >> 4, q = idx & 15;
            int kr = kt + r; if (kr >= S) kr = S - 1;
            uint4 v = *reinterpret_cast<const uint4*>(base + (size_t)kr * (3*D_MODEL) + D_MODEL + h * DH + q * 8);
            *reinterpret_cast<uint4*>(&KV[r * 68 + q * 4]) = v;
        }
        __syncthreads();

        // S = Q K^T
        float sf[8][4];
        #pragma unroll
        for (int ni = 0; ni < 8; ni++)
            sf[ni][0] = sf[ni][1] = sf[ni][2] = sf[ni][3] = 0.f;
        #pragma unroll
        for (int c = 0; c < 8; c++) {
            #pragma unroll
            for (int ni = 0; ni < 8; ni++) {
                uint32_t b0 = KV[(ni * 8 + g) * 68 + c * 8 + tg];
                uint32_t b1 = KV[(ni * 8 + g) * 68 + c * 8 + tg + 4];
                mma_f16(sf[ni][0], sf[ni][1], sf[ni][2], sf[ni][3],
                        qf[c][0], qf[c][1], qf[c][2], qf[c][3], b0, b1);
            }
        }

        // online softmax
        float mx0 = -1e30f, mx1 = -1e30f;
        #pragma unroll
        for (int ni = 0; ni < 8; ni++) {
            int c = kt + ni * 8 + tg * 2;
            if (c >= S)     { sf[ni][0] = -1e30f; sf[ni][2] = -1e30f; }
            if (c + 1 >= S) { sf[ni][1] = -1e30f; sf[ni][3] = -1e30f; }
            mx0 = fmaxf(mx0, fmaxf(sf[ni][0], sf[ni][1]));
            mx1 = fmaxf(mx1, fmaxf(sf[ni][2], sf[ni][3]));
        }
        mx0 = fmaxf(mx0, __shfl_xor_sync(0xffffffffu, mx0, 1));
        mx0 = fmaxf(mx0, __shfl_xor_sync(0xffffffffu, mx0, 2));
        mx1 = fmaxf(mx1, __shfl_xor_sync(0xffffffffu, mx1, 1));
        mx1 = fmaxf(mx1, __shfl_xor_sync(0xffffffffu, mx1, 2));
        const float M0 = fmaxf(m0, mx0), M1 = fmaxf(m1, mx1);
        const float sc0 = __expf(m0 - M0), sc1 = __expf(m1 - M1);
        float rs0 = 0.f, rs1 = 0.f;
        uint32_t ph[8][2];
        #pragma unroll
        for (int ni = 0; ni < 8; ni++) {
            float p00 = __expf(sf[ni][0] - M0);
            float p01 = __expf(sf[ni][1] - M0);
            float p10 = __expf(sf[ni][2] - M1);
            float p11 = __expf(sf[ni][3] - M1);
            rs0 += p00 + p01; rs1 += p10 + p11;
            ph[ni][0] = pack_h2(p00, p01);
            ph[ni][1] = pack_h2(p10, p11);
        }
        rs0 += __shfl_xor_sync(0xffffffffu, rs0, 1);
        rs0 += __shfl_xor_sync(0xffffffffu, rs0, 2);
        rs1 += __shfl_xor_sync(0xffffffffu, rs1, 1);
        rs1 += __shfl_xor_sync(0xffffffffu, rs1, 2);
        l0 = l0 * sc0 + rs0; l1 = l1 * sc1 + rs1;
        m0 = M0; m1 = M1;
        #pragma unroll
        for (int ni = 0; ni < 16; ni++) {
            o_acc[ni][0] *= sc0; o_acc[ni][1] *= sc0;
            o_acc[ni][2] *= sc1; o_acc[ni][3] *= sc1;
        }

        __syncthreads();
        // stage V
        #pragma unroll
        for (int it = 0; it < 8; it++) {
            int idx = it * 128 + tid;
            int r = idx >> 4, q = idx & 15;
            int kr = kt + r; if (kr >= S) kr = S - 1;
            uint4 v = *reinterpret_cast<const uint4*>(base + (size_t)kr * (3*D_MODEL) + 2 * D_MODEL + h * DH + q * 8);
            *reinterpret_cast<uint4*>(&KV[r * 68 + q * 4]) = v;
        }
        __syncthreads();

        // O += P V
        #pragma unroll
        for (int jc = 0; jc < 4; jc++) {
            uint32_t pa0 = ph[2*jc][0], pa1 = ph[2*jc][1];
            uint32_t pa2 = ph[2*jc+1][0], pa3 = ph[2*jc+1][1];
            #pragma unroll
            for (int nip = 0; nip < 8; nip++) {
                const int krow = jc * 16 + (lane & 15);
                const int dcol = nip * 16 + ((lane & 16) ? 8 : 0);
                const uint32_t addr = kvb + (uint32_t)(krow * 68 + (dcol >> 1)) * 4;
                uint32_t b00, b01, b10, b11;
                ldsm_x4_trans(b00, b01, b10, b11, addr);
                mma_f16(o_acc[nip*2][0], o_acc[nip*2][1], o_acc[nip*2][2], o_acc[nip*2][3],
                        pa0, pa1, pa2, pa3, b00, b01);
                mma_f16(o_acc[nip*2+1][0], o_acc[nip*2+1][1], o_acc[nip*2+1][2], o_acc[nip*2+1][3],
                        pa0, pa1, pa2, pa3, b10, b11);
            }
        }
    }

    const float inv0 = 1.f / l0, inv1 = 1.f / l1;
    const int r0 = q0 + wid * 16 + g, r1 = r0 + 8;
    #pragma unroll
    for (int ni = 0; ni < 16; ni++) {
        const int c = h * DH + ni * 8 + tg * 2;
        if (r0 < S)
            *reinterpret_cast<uint32_t*>(out + (size_t)(b * S + r0) * D_MODEL + c) =
                pack_h2(o_acc[ni][0] * inv0, o_acc[ni][1] * inv0);
        if (r1 < S)
            *reinterpret_cast<uint32_t*>(out + (size_t)(b * S + r1) * D_MODEL + c) =
                pack_h2(o_acc[ni][2] * inv1, o_acc[ni][3] * inv1);
    }
}

// ---------------- relay attention (16 tokens), fp16 in/out ----------------
__global__ __launch_bounds__(128)
void relay_attn(long rqkv_off, long ratt_off)
{
    const __half* __restrict__ rqkv = g_hscratch + rqkv_off;
    __half* __restrict__ rattn = g_hscratch + ratt_off;

    const int h = blockIdx.x, b = blockIdx.y;
    __shared__ float q[16][128], k[16][128], v[16][128];
    __shared__ float p[16][16];
    const int tid = threadIdx.x;

    // 16 rows x 128 halves per matrix = 256 uint4; 2 per thread per matrix
    #pragma unroll
    for (int it = 0; it < 2; it++) {
        int idx = it * 128 + tid;
        int r = idx >> 4, qq = idx & 15;
        const __half* rowp = rqkv + (size_t)(b * 16 + r) * (3 * D_MODEL) + h * DH + qq * 8;
        #pragma unroll
        for (int m = 0; m < 3; m++) {
            float* dst = (m == 0 ? &q[r][qq*8] : (m == 1 ? &k[r][qq*8] : &v[r][qq*8]));
            const __half* sp = rowp + m * D_MODEL;
            #pragma unroll
            for (int e = 0; e < 8; e++) dst[e] = __half2float(sp[e]);
        }
    }
    __syncthreads();

    #pragma unroll
    for (int t = 0; t < 2; t++) {
        int ij = tid * 2 + t;
        int i = ij >> 4, j = ij & 15;
        float s = 0.f;
        for (int d = 0; d < 128; d += 4) {
            float4 qa = *reinterpret_cast<float4*>(&q[i][d]);
            float4 ka = *reinterpret_cast<float4*>(&k[j][d]);
            s += qa.x*ka.x + qa.y*ka.y + qa.z*ka.z + qa.w*ka.w;
        }
        p[i][j] = s;
    }
    __syncthreads();

    if (tid < 16) {
        float mx = -1e30f;
        #pragma unroll
        for (int j = 0; j < 16; j++) mx = fmaxf(mx, p[tid][j]);
        float sum = 0.f; float e[16];
        #pragma unroll
        for (int j = 0; j < 16; j++) { e[j] = __expf(p[tid][j] - mx); sum += e[j]; }
        float inv = 1.0f / sum;
        #pragma unroll
        for (int j = 0; j < 16; j++) p[tid][j] = e[j] * inv;
    }
    __syncthreads();

    const int i = tid >> 3, c0 = (tid & 7) * 16;
    #pragma unroll
    for (int c = 0; c < 16; c += 2) {
        float o0 = 0.f, o1 = 0.f;
        #pragma unroll
        for (int j = 0; j < 16; j++) {
            o0 += p[i][j] * v[j][c0 + c];
            o1 += p[i][j] * v[j][c0 + c + 1];
        }
        *reinterpret_cast<uint32_t*>(rattn + (size_t)(b * 16 + i) * D_MODEL + h * DH + c0 + c) =
            pack_h2(o0, o1);
    }
}

// ---------------- small glue kernels ----------------
__global__ void init_xs(const float* __restrict__ x, const float* __restrict__ relay_emb)
{
    float* __restrict__ xs = g_scratch + OFF_XS;
    const int row = blockIdx.x;
    const int b = row / SEQ, sr = row % SEQ;
    const int grp = sr / (GRP + 1), w = sr % (GRP + 1);
    float4 val;
    if (w == 0)
        val = reinterpret_cast<const float4*>(relay_emb)[threadIdx.x];
    else {
        int t = grp * GRP + (w - 1);
        val = reinterpret_cast<const float4*>(x + (size_t)(b * TOKENS + t) * D_MODEL)[threadIdx.x];
    }
    reinterpret_cast<float4*>(xs + (size_t)row * D_MODEL)[threadIdx.x] = val;
}

__global__ void relay_scatter(long rprj_off, const float* __restrict__ bias)
{
    const float* __restrict__ rproj = g_scratch + rprj_off;
    float* __restrict__ xs = g_scratch + OFF_XS;
    const int row = blockIdx.x;
    float4 r = reinterpret_cast<const float4*>(rproj + (size_t)row * D_MODEL)[threadIdx.x];
    float4 bb = reinterpret_cast<const float4*>(bias)[threadIdx.x];
    float4* dst = reinterpret_cast<float4*>(xs + (size_t)row * (GRP + 1) * D_MODEL) + threadIdx.x;
    float4 c = *dst;
    c.x += r.x + bb.x; c.y += r.y + bb.y; c.z += r.z + bb.z; c.w += r.w + bb.w;
    *dst = c;
}

__global__ void final_out(float* __restrict__ out)
{
    const float* __restrict__ xs = g_scratch + OFF_XS;
    const int row = blockIdx.x;
    const int b = row / TOKENS, t = row % TOKENS;
    const int src = b * SEQ + (t >> 7) * (GRP + 1) + 1 + (t & 127);
    reinterpret_cast<float4*>(out + (size_t)row * D_MODEL)[threadIdx.x] =
        reinterpret_cast<const float4*>(xs + (size_t)src * D_MODEL)[threadIdx.x];
}

// ---------------- host side ----------------
static void launch_cvt(const float* src, long dst_off, long n)
{
    cvt_h<<<(unsigned)(n / 2048), 256>>>(src, dst_off, n);
}

static void launch_gemm(int ep, long a_off, long b_off, const float* bias,
                        long c_off, int M, int N, int K)
{
    dim3 grid(N / 128, (M + 127) / 128);
    switch (ep) {
        case 0:  gemm_h16<0><<<grid, 256>>>(a_off, b_off, bias, c_off, M, N, K); break;
        case 3:  gemm_h16<3><<<grid, 256>>>(a_off, b_off, bias, c_off, M, N, K); break;
        case 8:  gemm_h16<8><<<grid, 256>>>(a_off, b_off, bias, c_off, M, N, K); break;
        case 13: gemm_h16<13><<<grid, 256>>>(a_off, b_off, bias, c_off, M, N, K); break;
    }
}

extern "C" void kernel_launch(void* const* d_in, const int* in_sizes, int n_in,
                              void* d_out, int out_size)
{
    const float* x         = (const float*)d_in[0];
    const float* relay_emb = (const float*)d_in[1];
    const float* r_ln_g    = (const float*)d_in[2];
    const float* r_ln_b    = (const float*)d_in[3];
    const float* r_qkv     = (const float*)d_in[4];
    const float* r_ow      = (const float*)d_in[5];
    const float* r_ob      = (const float*)d_in[6];
    const float* l_ln_g    = (const float*)d_in[7];
    const float* l_ln_b    = (const float*)d_in[8];
    const float* l_qkv     = (const float*)d_in[9];
    const float* l_ow      = (const float*)d_in[10];
    const float* l_ob      = (const float*)d_in[11];
    const float* f_ln_g    = (const float*)d_in[12];
    const float* f_ln_b    = (const float*)d_in[13];
    const float* f_w1      = (const float*)d_in[14];
    const float* f_b1      = (const float*)d_in[15];
    const float* f_w2      = (const float*)d_in[16];
    const float* f_b2      = (const float*)d_in[17];

    // one-time weight conversion (fp32 -> fp16 scratch)
    for (int l = 0; l < DEPTH; l++) {
        long wb = HOFF_W + (long)l * WBLK;
        launch_cvt(r_qkv + (size_t)l * D_MODEL * 3 * D_MODEL, wb + W_RQKV, (long)D_MODEL * 3 * D_MODEL);
        launch_cvt(r_ow  + (size_t)l * D_MODEL * D_MODEL,     wb + W_ROW,  (long)D_MODEL * D_MODEL);
        launch_cvt(l_qkv + (size_t)l * D_MODEL * 3 * D_MODEL, wb + W_LQKV, (long)D_MODEL * 3 * D_MODEL);
        launch_cvt(l_ow  + (size_t)l * D_MODEL * D_MODEL,     wb + W_LOW,  (long)D_MODEL * D_MODEL);
        launch_cvt(f_w1  + (size_t)l * D_MODEL * DFF,         wb + W_FW1,  (long)D_MODEL * DFF);
        launch_cvt(f_w2  + (size_t)l * DFF * D_MODEL,         wb + W_FW2,  (long)DFF * D_MODEL);
    }

    init_xs<<<MROWS, 256>>>(x, relay_emb);

    for (int l = 0; l < DEPTH; l++) {
        const long wb = HOFF_W + (long)l * WBLK;

        // ---- relay attention over the 16 relay tokens per batch ----
        ln_kernel<<<32, 256>>>(OFF_XS, HOFF_RLN, r_ln_g + l * D_MODEL, r_ln_b + l * D_MODEL,
                               (long)(GRP + 1) * D_MODEL);
        launch_gemm(8, HOFF_RLN, wb + W_RQKV, nullptr, HOFF_RQKV, 32, 3 * D_MODEL, D_MODEL);
        relay_attn<<<dim3(HEADS, BATCH), 128>>>(HOFF_RQKV, HOFF_RATT);
        launch_gemm(0, HOFF_RATT, wb + W_ROW, nullptr, OFF_RPRJ, 32, D_MODEL, D_MODEL);
        relay_scatter<<<32, 256>>>(OFF_RPRJ, r_ob + l * D_MODEL);

        // ---- full attention over stitched sequence ----
        ln_kernel<<<MROWS, 256>>>(OFF_XS, HOFF_Y, l_ln_g + l * D_MODEL, l_ln_b + l * D_MODEL,
                                  D_MODEL);
        launch_gemm(8, HOFF_Y, wb + W_LQKV, nullptr, HOFF_QKV, MROWS, 3 * D_MODEL, D_MODEL);
        flash_attn_f16<<<dim3((SEQ + 63) / 64, HEADS, BATCH), 128>>>(HOFF_QKV, HOFF_ATT, SEQ);
        launch_gemm(3, HOFF_ATT, wb + W_LOW, l_ob + l * D_MODEL, OFF_XS, MROWS, D_MODEL, D_MODEL);

        // ---- FFN ----
        ln_kernel<<<MROWS, 256>>>(OFF_XS, HOFF_Y, f_ln_g + l * D_MODEL, f_ln_b + l * D_MODEL,
                                  D_MODEL);
        launch_gemm(13, HOFF_Y, wb + W_FW1, f_b1 + l * DFF, HOFF_FFN, MROWS, DFF, D_MODEL);
        launch_gemm(3, HOFF_FFN, wb + W_FW2, f_b2 + l * D_MODEL, OFF_XS, MROWS, D_MODEL, DFF);
    }

    final_out<<<BATCH * TOKENS, 256>>>((float*)d_out);
}

// round 14
// speedup vs baseline: 6.8589x; 1.1266x over previous
#include <cuda_runtime.h>
#include <cuda_fp16.h>
#include <cstdint>
#include <math.h>

// ---------------- problem constants ----------------
#define D_MODEL 1024
#define HEADS   8
#define DH      128
#define DEPTH   2
#define BATCH   2
#define TOKENS  2048
#define GRP     128
#define NGRP    16
#define SEQ     2064
#define MROWS   (BATCH*SEQ)    // 4128
#define DFF     4096

// ---------------- fp32 scratch ----------------
#define OFF_XS    0L
#define SZ_XS     ((long)MROWS*D_MODEL)
#define OFF_RPRJ  (OFF_XS + SZ_XS)
#define SZ_RPRJ   (32L*D_MODEL)
#define SCRATCH_FLOATS (OFF_RPRJ + SZ_RPRJ)

__device__ float g_scratch[SCRATCH_FLOATS];

// ---------------- fp16 scratch (offsets in halves) ----------------
#define WBLK      16777216L
#define W_RQKV    0L
#define W_ROW     3145728L
#define W_LQKV    4194304L
#define W_LOW     7340032L
#define W_FW1     8388608L
#define W_FW2     12582912L
#define HOFF_W    0L
#define SZ_W      (2*WBLK)
#define HOFF_Y    (HOFF_W + SZ_W)
#define SZ_HY     ((long)MROWS*D_MODEL)
#define HOFF_QKV  (HOFF_Y + SZ_HY)
#define SZ_HQKV   ((long)MROWS*3*D_MODEL)
#define HOFF_ATT  (HOFF_QKV + SZ_HQKV)
#define SZ_HATT   ((long)MROWS*D_MODEL)
#define HOFF_FFN  (HOFF_ATT + SZ_HATT)
#define SZ_HFFN   ((long)MROWS*DFF)
#define HOFF_RLN  (HOFF_FFN + SZ_HFFN)
#define SZ_HRLN   (32L*D_MODEL)
#define HOFF_RQKV (HOFF_RLN + SZ_HRLN)
#define SZ_HRQKV  (32L*3*D_MODEL)
#define HOFF_RATT (HOFF_RQKV + SZ_HRQKV)
#define SZ_HRATT  (32L*D_MODEL)
#define HSCRATCH_HALVES (HOFF_RATT + SZ_HRATT)

__device__ __align__(16) __half g_hscratch[HSCRATCH_HALVES];

// ---------------- helpers ----------------
__device__ __forceinline__ uint32_t smem_u32(const void* p) {
    uint32_t a;
    asm("{ .reg .u64 t; cvta.to.shared.u64 t, %1; cvt.u32.u64 %0, t; }" : "=r"(a) : "l"(p));
    return a;
}

__device__ __forceinline__ uint32_t pack_h2(float lo, float hi) {
    __half2 h = __floats2half2_rn(lo, hi);   // low 16 bits = lo
    return *reinterpret_cast<uint32_t*>(&h);
}

__device__ __forceinline__ void mma_f16(float& d0, float& d1, float& d2, float& d3,
                                        uint32_t a0, uint32_t a1, uint32_t a2, uint32_t a3,
                                        uint32_t b0, uint32_t b1)
{
    asm volatile("mma.sync.aligned.m16n8k16.row.col.f32.f16.f16.f32 "
                 "{%0,%1,%2,%3}, {%4,%5,%6,%7}, {%8,%9}, {%0,%1,%2,%3};\n"
                 : "+f"(d0), "+f"(d1), "+f"(d2), "+f"(d3)
                 : "r"(a0), "r"(a1), "r"(a2), "r"(a3), "r"(b0), "r"(b1));
}

__device__ __forceinline__ void ldsm_x4(uint32_t& r0, uint32_t& r1,
                                        uint32_t& r2, uint32_t& r3, uint32_t addr)
{
    asm volatile("ldmatrix.sync.aligned.m8n8.x4.shared.b16 {%0,%1,%2,%3}, [%4];"
                 : "=r"(r0), "=r"(r1), "=r"(r2), "=r"(r3) : "r"(addr));
}

__device__ __forceinline__ void ldsm_x4_trans(uint32_t& r0, uint32_t& r1,
                                              uint32_t& r2, uint32_t& r3, uint32_t addr)
{
    asm volatile("ldmatrix.sync.aligned.m8n8.x4.trans.shared.b16 {%0,%1,%2,%3}, [%4];"
                 : "=r"(r0), "=r"(r1), "=r"(r2), "=r"(r3) : "r"(addr));
}

// ---------------- fp32 -> fp16 weight conversion ----------------
__global__ __launch_bounds__(256)
void cvt_h(const float* __restrict__ src, long dst_off, long n)
{
    __half* __restrict__ dst = g_hscratch + dst_off;
    long i = ((long)blockIdx.x * 256 + threadIdx.x) * 8;
    float4 a = *reinterpret_cast<const float4*>(src + i);
    float4 b = *reinterpret_cast<const float4*>(src + i + 4);
    uint4 u = make_uint4(pack_h2(a.x, a.y), pack_h2(a.z, a.w),
                         pack_h2(b.x, b.y), pack_h2(b.z, b.w));
    *reinterpret_cast<uint4*>(dst + i) = u;
}

// ================= fp16-in fp16/fp32-out mma GEMM =================
// C = A(MxK) @ B(KxN); A,B fp16 (g_hscratch offsets), C fp32 (g_scratch) or fp16 (bit 8).
// EP bits: 1=+bias(f32), 2=residual-accumulate(f32 C), 4=leaky_relu, 8=fp16 output
// Block 128x128, BK=32, 8 warps (2x4), warp tile 64x32, m16n8k16.
// A-frags via ldmatrix.x4 (rows x stride-80B -> conflict-free phases).
template<int EP>
__global__ __launch_bounds__(256)
void gemm_h16(long a_off, long b_off, const float* __restrict__ bias, long c_off,
              int M, int N, int K)
{
    __shared__ __align__(16) uint32_t As[2][128 * 20];   // [m][16 data + 4 pad] half2 words
    __shared__ __align__(16) uint32_t Bs[2][32 * 68];    // [k][64 data + 4 pad] half2 words

    const __half* __restrict__ A = g_hscratch + a_off;
    const __half* __restrict__ B = g_hscratch + b_off;

    const int tid = threadIdx.x;
    const int lane = tid & 31;
    const int wid = tid >> 5;
    const int warp_m = wid >> 2;
    const int warp_n = wid & 3;
    const int g  = lane >> 2;
    const int tg = lane & 3;
    const int bm = blockIdx.y * 128;
    const int bn = blockIdx.x * 128;

    const uint32_t bsA = smem_u32(&As[0][0]);
    const uint32_t bsB = smem_u32(&Bs[0][0]);

    // ldmatrix.x4 A lane mapping: rowoff in 0..15, kword 0 or 4 (half2 words)
    const int a_rowoff = ((lane >> 3) & 1) * 8 + (lane & 7);
    const int a_kword  = (lane >> 4) * 4;

    // staging indices
    int a_r[2], a_q[2], a_gr[2], b_r[2], b_q[2];
    #pragma unroll
    for (int i = 0; i < 2; i++) {
        int idx = tid + i * 256;
        a_r[i] = idx >> 2;  a_q[i] = idx & 3;
        b_r[i] = idx >> 4;  b_q[i] = idx & 15;
        int r = bm + a_r[i];
        a_gr[i] = (r < M) ? r : (M - 1);
    }

    float acc[4][4][4];
    #pragma unroll
    for (int mi = 0; mi < 4; mi++)
        #pragma unroll
        for (int ni = 0; ni < 4; ni++)
            #pragma unroll
            for (int q = 0; q < 4; q++) acc[mi][ni][q] = 0.f;

    const int nk = K / 32;
    uint4 aR[2], bR[2];

    #pragma unroll
    for (int i = 0; i < 2; i++) {
        aR[i] = *reinterpret_cast<const uint4*>(A + (size_t)a_gr[i] * K + a_q[i] * 8);
        bR[i] = *reinterpret_cast<const uint4*>(B + (size_t)b_r[i] * N + bn + b_q[i] * 8);
    }
    #pragma unroll
    for (int i = 0; i < 2; i++) {
        *reinterpret_cast<uint4*>(&As[0][a_r[i] * 20 + a_q[i] * 4]) = aR[i];
        *reinterpret_cast<uint4*>(&Bs[0][b_r[i] * 68 + b_q[i] * 4]) = bR[i];
    }
    __syncthreads();

    for (int s = 0; s < nk; s++) {
        const int cur = s & 1;
        if (s + 1 < nk) {
            const int k0 = (s + 1) * 32;
            #pragma unroll
            for (int i = 0; i < 2; i++) {
                aR[i] = *reinterpret_cast<const uint4*>(A + (size_t)a_gr[i] * K + k0 + a_q[i] * 8);
                bR[i] = *reinterpret_cast<const uint4*>(B + (size_t)(k0 + b_r[i]) * N + bn + b_q[i] * 8);
            }
        }

        const uint32_t abase = bsA + (uint32_t)cur * (128 * 20 * 4);
        const uint32_t bbase = bsB + (uint32_t)cur * (32 * 68 * 4);
        #pragma unroll
        for (int ks = 0; ks < 2; ks++) {
            uint32_t bf[4][2];
            #pragma unroll
            for (int nip = 0; nip < 2; nip++) {
                const int krow = ks * 16 + (lane & 15);
                const int ncol = warp_n * 32 + nip * 16 + ((lane & 16) ? 8 : 0);
                const uint32_t addr = bbase + (uint32_t)(krow * 68 + (ncol >> 1)) * 4;
                ldsm_x4_trans(bf[nip*2][0], bf[nip*2][1], bf[nip*2+1][0], bf[nip*2+1][1], addr);
            }
            #pragma unroll
            for (int mi = 0; mi < 4; mi++) {
                const int r = warp_m * 64 + mi * 16 + a_rowoff;
                const uint32_t aaddr = abase + (uint32_t)(r * 20 + ks * 8 + a_kword) * 4;
                uint32_t a0, a1, a2, a3;
                ldsm_x4(a0, a1, a2, a3, aaddr);
                #pragma unroll
                for (int ni = 0; ni < 4; ni++)
                    mma_f16(acc[mi][ni][0], acc[mi][ni][1], acc[mi][ni][2], acc[mi][ni][3],
                            a0, a1, a2, a3, bf[ni][0], bf[ni][1]);
            }
        }

        if (s + 1 < nk) {
            const int nxt = (s + 1) & 1;
            #pragma unroll
            for (int i = 0; i < 2; i++) {
                *reinterpret_cast<uint4*>(&As[nxt][a_r[i] * 20 + a_q[i] * 4]) = aR[i];
                *reinterpret_cast<uint4*>(&Bs[nxt][b_r[i] * 68 + b_q[i] * 4]) = bR[i];
            }
        }
        __syncthreads();
    }

    // epilogue
    #pragma unroll
    for (int mi = 0; mi < 4; mi++) {
        #pragma unroll
        for (int half = 0; half < 2; half++) {
            const int r = bm + warp_m * 64 + mi * 16 + g + half * 8;
            if (r >= M) continue;
            #pragma unroll
            for (int ni = 0; ni < 4; ni++) {
                float v0 = acc[mi][ni][half * 2 + 0];
                float v1 = acc[mi][ni][half * 2 + 1];
                const int c = bn + warp_n * 32 + ni * 8 + tg * 2;
                if (EP & 1) { v0 += bias[c]; v1 += bias[c + 1]; }
                if (EP & 4) {
                    v0 = v0 > 0.f ? v0 : 0.01f * v0;
                    v1 = v1 > 0.f ? v1 : 0.01f * v1;
                }
                if (EP & 8) {
                    __half* cp = g_hscratch + c_off + (size_t)r * N + c;
                    *reinterpret_cast<uint32_t*>(cp) = pack_h2(v0, v1);
                } else {
                    float* cp = g_scratch + c_off + (size_t)r * N + c;
                    if (EP & 2) {
                        float2 old = *reinterpret_cast<float2*>(cp);
                        v0 += old.x; v1 += old.y;
                    }
                    *reinterpret_cast<float2*>(cp) = make_float2(v0, v1);
                }
            }
        }
    }
}

// ---------------- LayerNorm: fp32 in (strided), fp16 out [row][1024] ----------------
__global__ __launch_bounds__(256)
void ln_kernel(long in_off, long out_off_h,
               const float* __restrict__ gamma, const float* __restrict__ beta,
               long in_stride)
{
    const float* __restrict__ in = g_scratch + in_off;
    __half* __restrict__ out = g_hscratch + out_off_h;

    const int row = blockIdx.x;
    const int tid = threadIdx.x;
    const float4 v = reinterpret_cast<const float4*>(in + (size_t)row * in_stride)[tid];

    float s  = v.x + v.y + v.z + v.w;
    float sq = v.x*v.x + v.y*v.y + v.z*v.z + v.w*v.w;
    #pragma unroll
    for (int o = 16; o > 0; o >>= 1) {
        s  += __shfl_xor_sync(0xffffffffu, s,  o);
        sq += __shfl_xor_sync(0xffffffffu, sq, o);
    }
    __shared__ float ss[8], sqs[8];
    const int warp = tid >> 5;
    if ((tid & 31) == 0) { ss[warp] = s; sqs[warp] = sq; }
    __syncthreads();
    float ts = 0.f, tq = 0.f;
    #pragma unroll
    for (int w = 0; w < 8; w++) { ts += ss[w]; tq += sqs[w]; }
    const float mean = ts * (1.0f / D_MODEL);
    const float var  = tq * (1.0f / D_MODEL) - mean * mean;
    const float rstd = rsqrtf(var + 1e-5f);

    const float4 g4 = reinterpret_cast<const float4*>(gamma)[tid];
    const float4 b4 = reinterpret_cast<const float4*>(beta)[tid];
    float o0 = (v.x - mean) * rstd * g4.x + b4.x;
    float o1 = (v.y - mean) * rstd * g4.y + b4.y;
    float o2 = (v.z - mean) * rstd * g4.z + b4.z;
    float o3 = (v.w - mean) * rstd * g4.w + b4.w;
    *reinterpret_cast<uint2*>(out + (size_t)row * D_MODEL + tid * 4) =
        make_uint2(pack_h2(o0, o1), pack_h2(o2, o3));
}

// ---------------- fp16 flash attention (unscaled dots!), fp16 in/out ----------------
// Br=64, Bc=64, 4 warps. Separate K/V buffers: 2 syncs per tile instead of 4,
// K+V staged together (MLP 16).
__global__ __launch_bounds__(128)
void flash_attn_f16(long qkv_off, long out_off, int S)
{
    __shared__ __align__(16) uint32_t KS[64 * 68];
    __shared__ __align__(16) uint32_t VS[64 * 68];

    const __half* __restrict__ qkv = g_hscratch + qkv_off;
    __half* __restrict__ out = g_hscratch + out_off;

    const int b = blockIdx.z, h = blockIdx.y;
    const int q0 = blockIdx.x * 64;
    const int tid = threadIdx.x;
    const int lane = tid & 31, wid = tid >> 5;
    const int g = lane >> 2, tg = lane & 3;
    const __half* base = qkv + (size_t)b * S * (3 * D_MODEL);
    const uint32_t vsb = smem_u32(&VS[0]);

    // ---- stage Q into KS, lift to A-frags ----
    #pragma unroll
    for (int it = 0; it < 8; it++) {
        int idx = it * 128 + tid;
        int r = idx >> 4, q = idx & 15;
        int qr = q0 + r; if (qr >= S) qr = S - 1;
        uint4 v = *reinterpret_cast<const uint4*>(base + (size_t)qr * (3*D_MODEL) + h * DH + q * 8);
        *reinterpret_cast<uint4*>(&KS[r * 68 + q * 4]) = v;
    }
    __syncthreads();
    uint32_t qf[8][4];
    {
        const int qrow = wid * 16 + g;
        #pragma unroll
        for (int c = 0; c < 8; c++) {
            qf[c][0] = KS[qrow * 68 + c * 8 + tg];
            qf[c][1] = KS[(qrow + 8) * 68 + c * 8 + tg];
            qf[c][2] = KS[qrow * 68 + c * 8 + tg + 4];
            qf[c][3] = KS[(qrow + 8) * 68 + c * 8 + tg + 4];
        }
    }

    float o_acc[16][4];
    #pragma unroll
    for (int ni = 0; ni < 16; ni++)
        o_acc[ni][0] = o_acc[ni][1] = o_acc[ni][2] = o_acc[ni][3] = 0.f;
    float m0 = -1e30f, m1 = -1e30f, l0 = 0.f, l1 = 0.f;

    for (int kt = 0; kt < S; kt += 64) {
        __syncthreads();   // prior S-reads of KS (incl. Q lift) and PV-reads of VS done
        // stage K and V together
        #pragma unroll
        for (int it = 0; it < 8; it++) {
            int idx = it * 128 + tid;
            int r = idx >> 4, q = idx & 15;
            int kr = kt + r; if (kr >= S) kr = S - 1;
            const __half* rp = base + (size_t)kr * (3*D_MODEL) + h * DH + q * 8;
            uint4 vk = *reinterpret_cast<const uint4*>(rp + D_MODEL);
            uint4 vv = *reinterpret_cast<const uint4*>(rp + 2 * D_MODEL);
            *reinterpret_cast<uint4*>(&KS[r * 68 + q * 4]) = vk;
            *reinterpret_cast<uint4*>(&VS[r * 68 + q * 4]) = vv;
        }
        __syncthreads();

        // S = Q K^T
        float sf[8][4];
        #pragma unroll
        for (int ni = 0; ni < 8; ni++)
            sf[ni][0] = sf[ni][1] = sf[ni][2] = sf[ni][3] = 0.f;
        #pragma unroll
        for (int c = 0; c < 8; c++) {
            #pragma unroll
            for (int ni = 0; ni < 8; ni++) {
                uint32_t b0 = KS[(ni * 8 + g) * 68 + c * 8 + tg];
                uint32_t b1 = KS[(ni * 8 + g) * 68 + c * 8 + tg + 4];
                mma_f16(sf[ni][0], sf[ni][1], sf[ni][2], sf[ni][3],
                        qf[c][0], qf[c][1], qf[c][2], qf[c][3], b0, b1);
            }
        }

        // online softmax
        float mx0 = -1e30f, mx1 = -1e30f;
        #pragma unroll
        for (int ni = 0; ni < 8; ni++) {
            int c = kt + ni * 8 + tg * 2;
            if (c >= S)     { sf[ni][0] = -1e30f; sf[ni][2] = -1e30f; }
            if (c + 1 >= S) { sf[ni][1] = -1e30f; sf[ni][3] = -1e30f; }
            mx0 = fmaxf(mx0, fmaxf(sf[ni][0], sf[ni][1]));
            mx1 = fmaxf(mx1, fmaxf(sf[ni][2], sf[ni][3]));
        }
        mx0 = fmaxf(mx0, __shfl_xor_sync(0xffffffffu, mx0, 1));
        mx0 = fmaxf(mx0, __shfl_xor_sync(0xffffffffu, mx0, 2));
        mx1 = fmaxf(mx1, __shfl_xor_sync(0xffffffffu, mx1, 1));
        mx1 = fmaxf(mx1, __shfl_xor_sync(0xffffffffu, mx1, 2));
        const float M0 = fmaxf(m0, mx0), M1 = fmaxf(m1, mx1);
        const float sc0 = __expf(m0 - M0), sc1 = __expf(m1 - M1);
        float rs0 = 0.f, rs1 = 0.f;
        uint32_t ph[8][2];
        #pragma unroll
        for (int ni = 0; ni < 8; ni++) {
            float p00 = __expf(sf[ni][0] - M0);
            float p01 = __expf(sf[ni][1] - M0);
            float p10 = __expf(sf[ni][2] - M1);
            float p11 = __expf(sf[ni][3] - M1);
            rs0 += p00 + p01; rs1 += p10 + p11;
            ph[ni][0] = pack_h2(p00, p01);
            ph[ni][1] = pack_h2(p10, p11);
        }
        rs0 += __shfl_xor_sync(0xffffffffu, rs0, 1);
        rs0 += __shfl_xor_sync(0xffffffffu, rs0, 2);
        rs1 += __shfl_xor_sync(0xffffffffu, rs1, 1);
        rs1 += __shfl_xor_sync(0xffffffffu, rs1, 2);
        l0 = l0 * sc0 + rs0; l1 = l1 * sc1 + rs1;
        m0 = M0; m1 = M1;
        #pragma unroll
        for (int ni = 0; ni < 16; ni++) {
            o_acc[ni][0] *= sc0; o_acc[ni][1] *= sc0;
            o_acc[ni][2] *= sc1; o_acc[ni][3] *= sc1;
        }

        // O += P V  (VS untouched by staging until next loop-top sync)
        #pragma unroll
        for (int jc = 0; jc < 4; jc++) {
            uint32_t pa0 = ph[2*jc][0], pa1 = ph[2*jc][1];
            uint32_t pa2 = ph[2*jc+1][0], pa3 = ph[2*jc+1][1];
            #pragma unroll
            for (int nip = 0; nip < 8; nip++) {
                const int krow = jc * 16 + (lane & 15);
                const int dcol = nip * 16 + ((lane & 16) ? 8 : 0);
                const uint32_t addr = vsb + (uint32_t)(krow * 68 + (dcol >> 1)) * 4;
                uint32_t b00, b01, b10, b11;
                ldsm_x4_trans(b00, b01, b10, b11, addr);
                mma_f16(o_acc[nip*2][0], o_acc[nip*2][1], o_acc[nip*2][2], o_acc[nip*2][3],
                        pa0, pa1, pa2, pa3, b00, b01);
                mma_f16(o_acc[nip*2+1][0], o_acc[nip*2+1][1], o_acc[nip*2+1][2], o_acc[nip*2+1][3],
                        pa0, pa1, pa2, pa3, b10, b11);
            }
        }
    }

    const float inv0 = 1.f / l0, inv1 = 1.f / l1;
    const int r0 = q0 + wid * 16 + g, r1 = r0 + 8;
    #pragma unroll
    for (int ni = 0; ni < 16; ni++) {
        const int c = h * DH + ni * 8 + tg * 2;
        if (r0 < S)
            *reinterpret_cast<uint32_t*>(out + (size_t)(b * S + r0) * D_MODEL + c) =
                pack_h2(o_acc[ni][0] * inv0, o_acc[ni][1] * inv0);
        if (r1 < S)
            *reinterpret_cast<uint32_t*>(out + (size_t)(b * S + r1) * D_MODEL + c) =
                pack_h2(o_acc[ni][2] * inv1, o_acc[ni][3] * inv1);
    }
}

// ---------------- relay attention (16 tokens), fp16 in/out ----------------
__global__ __launch_bounds__(128)
void relay_attn(long rqkv_off, long ratt_off)
{
    const __half* __restrict__ rqkv = g_hscratch + rqkv_off;
    __half* __restrict__ rattn = g_hscratch + ratt_off;

    const int h = blockIdx.x, b = blockIdx.y;
    __shared__ float q[16][128], k[16][128], v[16][128];
    __shared__ float p[16][16];
    const int tid = threadIdx.x;

    #pragma unroll
    for (int it = 0; it < 2; it++) {
        int idx = it * 128 + tid;
        int r = idx >> 4, qq = idx & 15;
        const __half* rowp = rqkv + (size_t)(b * 16 + r) * (3 * D_MODEL) + h * DH + qq * 8;
        #pragma unroll
        for (int m = 0; m < 3; m++) {
            float* dst = (m == 0 ? &q[r][qq*8] : (m == 1 ? &k[r][qq*8] : &v[r][qq*8]));
            const __half* sp = rowp + m * D_MODEL;
            #pragma unroll
            for (int e = 0; e < 8; e++) dst[e] = __half2float(sp[e]);
        }
    }
    __syncthreads();

    #pragma unroll
    for (int t = 0; t < 2; t++) {
        int ij = tid * 2 + t;
        int i = ij >> 4, j = ij & 15;
        float s = 0.f;
        for (int d = 0; d < 128; d += 4) {
            float4 qa = *reinterpret_cast<float4*>(&q[i][d]);
            float4 ka = *reinterpret_cast<float4*>(&k[j][d]);
            s += qa.x*ka.x + qa.y*ka.y + qa.z*ka.z + qa.w*ka.w;
        }
        p[i][j] = s;
    }
    __syncthreads();

    if (tid < 16) {
        float mx = -1e30f;
        #pragma unroll
        for (int j = 0; j < 16; j++) mx = fmaxf(mx, p[tid][j]);
        float sum = 0.f; float e[16];
        #pragma unroll
        for (int j = 0; j < 16; j++) { e[j] = __expf(p[tid][j] - mx); sum += e[j]; }
        float inv = 1.0f / sum;
        #pragma unroll
        for (int j = 0; j < 16; j++) p[tid][j] = e[j] * inv;
    }
    __syncthreads();

    const int i = tid >> 3, c0 = (tid & 7) * 16;
    #pragma unroll
    for (int c = 0; c < 16; c += 2) {
        float o0 = 0.f, o1 = 0.f;
        #pragma unroll
        for (int j = 0; j < 16; j++) {
            o0 += p[i][j] * v[j][c0 + c];
            o1 += p[i][j] * v[j][c0 + c + 1];
        }
        *reinterpret_cast<uint32_t*>(rattn + (size_t)(b * 16 + i) * D_MODEL + h * DH + c0 + c) =
            pack_h2(o0, o1);
    }
}

// ---------------- small glue kernels ----------------
__global__ void init_xs(const float* __restrict__ x, const float* __restrict__ relay_emb)
{
    float* __restrict__ xs = g_scratch + OFF_XS;
    const int row = blockIdx.x;
    const int b = row / SEQ, sr = row % SEQ;
    const int grp = sr / (GRP + 1), w = sr % (GRP + 1);
    float4 val;
    if (w == 0)
        val = reinterpret_cast<const float4*>(relay_emb)[threadIdx.x];
    else {
        int t = grp * GRP + (w - 1);
        val = reinterpret_cast<const float4*>(x + (size_t)(b * TOKENS + t) * D_MODEL)[threadIdx.x];
    }
    reinterpret_cast<float4*>(xs + (size_t)row * D_MODEL)[threadIdx.x] = val;
}

__global__ void relay_scatter(long rprj_off, const float* __restrict__ bias)
{
    const float* __restrict__ rproj = g_scratch + rprj_off;
    float* __restrict__ xs = g_scratch + OFF_XS;
    const int row = blockIdx.x;
    float4 r = reinterpret_cast<const float4*>(rproj + (size_t)row * D_MODEL)[threadIdx.x];
    float4 bb = reinterpret_cast<const float4*>(bias)[threadIdx.x];
    float4* dst = reinterpret_cast<float4*>(xs + (size_t)row * (GRP + 1) * D_MODEL) + threadIdx.x;
    float4 c = *dst;
    c.x += r.x + bb.x; c.y += r.y + bb.y; c.z += r.z + bb.z; c.w += r.w + bb.w;
    *dst = c;
}

__global__ void final_out(float* __restrict__ out)
{
    const float* __restrict__ xs = g_scratch + OFF_XS;
    const int row = blockIdx.x;
    const int b = row / TOKENS, t = row % TOKENS;
    const int src = b * SEQ + (t >> 7) * (GRP + 1) + 1 + (t & 127);
    reinterpret_cast<float4*>(out + (size_t)row * D_MODEL)[threadIdx.x] =
        reinterpret_cast<const float4*>(xs + (size_t)src * D_MODEL)[threadIdx.x];
}

// ---------------- host side ----------------
static void launch_cvt(const float* src, long dst_off, long n)
{
    cvt_h<<<(unsigned)(n / 2048), 256>>>(src, dst_off, n);
}

static void launch_gemm(int ep, long a_off, long b_off, const float* bias,
                        long c_off, int M, int N, int K)
{
    dim3 grid(N / 128, (M + 127) / 128);
    switch (ep) {
        case 0:  gemm_h16<0><<<grid, 256>>>(a_off, b_off, bias, c_off, M, N, K); break;
        case 3:  gemm_h16<3><<<grid, 256>>>(a_off, b_off, bias, c_off, M, N, K); break;
        case 8:  gemm_h16<8><<<grid, 256>>>(a_off, b_off, bias, c_off, M, N, K); break;
        case 13: gemm_h16<13><<<grid, 256>>>(a_off, b_off, bias, c_off, M, N, K); break;
    }
}

extern "C" void kernel_launch(void* const* d_in, const int* in_sizes, int n_in,
                              void* d_out, int out_size)
{
    const float* x         = (const float*)d_in[0];
    const float* relay_emb = (const float*)d_in[1];
    const float* r_ln_g    = (const float*)d_in[2];
    const float* r_ln_b    = (const float*)d_in[3];
    const float* r_qkv     = (const float*)d_in[4];
    const float* r_ow      = (const float*)d_in[5];
    const float* r_ob      = (const float*)d_in[6];
    const float* l_ln_g    = (const float*)d_in[7];
    const float* l_ln_b    = (const float*)d_in[8];
    const float* l_qkv     = (const float*)d_in[9];
    const float* l_ow      = (const float*)d_in[10];
    const float* l_ob      = (const float*)d_in[11];
    const float* f_ln_g    = (const float*)d_in[12];
    const float* f_ln_b    = (const float*)d_in[13];
    const float* f_w1      = (const float*)d_in[14];
    const float* f_b1      = (const float*)d_in[15];
    const float* f_w2      = (const float*)d_in[16];
    const float* f_b2      = (const float*)d_in[17];

    // one-time weight conversion (fp32 -> fp16 scratch)
    for (int l = 0; l < DEPTH; l++) {
        long wb = HOFF_W + (long)l * WBLK;
        launch_cvt(r_qkv + (size_t)l * D_MODEL * 3 * D_MODEL, wb + W_RQKV, (long)D_MODEL * 3 * D_MODEL);
        launch_cvt(r_ow  + (size_t)l * D_MODEL * D_MODEL,     wb + W_ROW,  (long)D_MODEL * D_MODEL);
        launch_cvt(l_qkv + (size_t)l * D_MODEL * 3 * D_MODEL, wb + W_LQKV, (long)D_MODEL * 3 * D_MODEL);
        launch_cvt(l_ow  + (size_t)l * D_MODEL * D_MODEL,     wb + W_LOW,  (long)D_MODEL * D_MODEL);
        launch_cvt(f_w1  + (size_t)l * D_MODEL * DFF,         wb + W_FW1,  (long)D_MODEL * DFF);
        launch_cvt(f_w2  + (size_t)l * DFF * D_MODEL,         wb + W_FW2,  (long)DFF * D_MODEL);
    }

    init_xs<<<MROWS, 256>>>(x, relay_emb);

    for (int l = 0; l < DEPTH; l++) {
        const long wb = HOFF_W + (long)l * WBLK;

        // ---- relay attention over the 16 relay tokens per batch ----
        ln_kernel<<<32, 256>>>(OFF_XS, HOFF_RLN, r_ln_g + l * D_MODEL, r_ln_b + l * D_MODEL,
                               (long)(GRP + 1) * D_MODEL);
        launch_gemm(8, HOFF_RLN, wb + W_RQKV, nullptr, HOFF_RQKV, 32, 3 * D_MODEL, D_MODEL);
        relay_attn<<<dim3(HEADS, BATCH), 128>>>(HOFF_RQKV, HOFF_RATT);
        launch_gemm(0, HOFF_RATT, wb + W_ROW, nullptr, OFF_RPRJ, 32, D_MODEL, D_MODEL);
        relay_scatter<<<32, 256>>>(OFF_RPRJ, r_ob + l * D_MODEL);

        // ---- full attention over stitched sequence ----
        ln_kernel<<<MROWS, 256>>>(OFF_XS, HOFF_Y, l_ln_g + l * D_MODEL, l_ln_b + l * D_MODEL,
                                  D_MODEL);
        launch_gemm(8, HOFF_Y, wb + W_LQKV, nullptr, HOFF_QKV, MROWS, 3 * D_MODEL, D_MODEL);
        flash_attn_f16<<<dim3((SEQ + 63) / 64, HEADS, BATCH), 128>>>(HOFF_QKV, HOFF_ATT, SEQ);
        launch_gemm(3, HOFF_ATT, wb + W_LOW, l_ob + l * D_MODEL, OFF_XS, MROWS, D_MODEL, D_MODEL);

        // ---- FFN ----
        ln_kernel<<<MROWS, 256>>>(OFF_XS, HOFF_Y, f_ln_g + l * D_MODEL, f_ln_b + l * D_MODEL,
                                  D_MODEL);
        launch_gemm(13, HOFF_Y, wb + W_FW1, f_b1 + l * DFF, HOFF_FFN, MROWS, DFF, D_MODEL);
        launch_gemm(3, HOFF_FFN, wb + W_FW2, f_b2 + l * D_MODEL, OFF_XS, MROWS, D_MODEL, DFF);
    }

    final_out<<<BATCH * TOKENS, 256>>>((float*)d_out);
}